// round 13
// baseline (speedup 1.0000x reference)
#include <cuda_runtime.h>
#include <cuda_bf16.h>
#include <cstdint>

// ---------------- problem constants ----------------
#define Bb 2
#define Ss 4096
#define Dm 768
#define Hh 12
#define HD 64
#define BLKSZ 32
#define NBR 128
#define NUMBLK 1024
#define MBT (Bb*Hh)        // 24
#define MROWS (Bb*Ss)      // 8192

typedef unsigned long long ull;

__device__ __forceinline__ uint32_t smem_u32(const void* p) {
    uint32_t a;
    asm("{ .reg .u64 t; cvta.to.shared.u64 t, %1; cvt.u32.u64 %0, t; }" : "=r"(a) : "l"(p));
    return a;
}

// ---------------- mbarrier + bulk-copy helpers ----------------
#define MB_INIT(mb, c) \
    asm volatile("mbarrier.init.shared.b64 [%0], %1;" :: "r"((uint32_t)(mb)), "r"((uint32_t)(c)) : "memory")
#define MB_ARRIVE_TX(mb, bytes) \
    asm volatile("mbarrier.arrive.expect_tx.shared.b64 _, [%0], %1;" :: "r"((uint32_t)(mb)), "r"((uint32_t)(bytes)) : "memory")
#define BULK_G2S(dst, src, size, mb) \
    asm volatile("cp.async.bulk.shared::cluster.global.mbarrier::complete_tx::bytes [%0], [%1], %2, [%3];" \
        :: "r"((uint32_t)(dst)), "l"(src), "r"((uint32_t)(size)), "r"((uint32_t)(mb)) : "memory")
#define MB_WAIT(mb, ph) do { \
    uint32_t _m = (uint32_t)(mb); uint32_t _p = (uint32_t)(ph); uint32_t _d; \
    asm volatile("{\n\t.reg .pred p;\n\tmbarrier.try_wait.parity.acquire.cta.shared::cta.b64 p, [%1], %2;\n\tselp.b32 %0, 1, 0, p;\n\t}" \
        : "=r"(_d) : "r"(_m), "r"(_p) : "memory"); \
    if (!_d) { \
        asm volatile("{\n\t.reg .pred P1;\n\tWL_%=:\n\tmbarrier.try_wait.parity.acquire.cta.shared::cta.b64 P1, [%0], %1, 0x989680;\n\t@P1 bra.uni WD_%=;\n\tbra.uni WL_%=;\n\tWD_%=:\n\t}" \
            :: "r"(_m), "r"(_p) : "memory"); \
    } } while (0)

// ---------------- mma.sync helpers ----------------
__device__ __forceinline__ void ldsm4(uint32_t &r0, uint32_t &r1, uint32_t &r2, uint32_t &r3, uint32_t addr) {
    asm volatile("ldmatrix.sync.aligned.m8n8.x4.shared.b16 {%0,%1,%2,%3}, [%4];"
        : "=r"(r0), "=r"(r1), "=r"(r2), "=r"(r3) : "r"(addr));
}
__device__ __forceinline__ void ldsm2(uint32_t &r0, uint32_t &r1, uint32_t addr) {
    asm volatile("ldmatrix.sync.aligned.m8n8.x2.shared.b16 {%0,%1}, [%2];"
        : "=r"(r0), "=r"(r1) : "r"(addr));
}
__device__ __forceinline__ void ldsm4t(uint32_t &r0, uint32_t &r1, uint32_t &r2, uint32_t &r3, uint32_t addr) {
    asm volatile("ldmatrix.sync.aligned.m8n8.x4.trans.shared.b16 {%0,%1,%2,%3}, [%4];"
        : "=r"(r0), "=r"(r1), "=r"(r2), "=r"(r3) : "r"(addr));
}
__device__ __forceinline__ void mma16816(float* c,
    uint32_t a0, uint32_t a1, uint32_t a2, uint32_t a3, uint32_t b0, uint32_t b1) {
    asm volatile("mma.sync.aligned.m16n8k16.row.col.f32.bf16.bf16.f32 "
        "{%0,%1,%2,%3}, {%4,%5,%6,%7}, {%8,%9}, {%0,%1,%2,%3};"
        : "+f"(c[0]), "+f"(c[1]), "+f"(c[2]), "+f"(c[3])
        : "r"(a0), "r"(a1), "r"(a2), "r"(a3), "r"(b0), "r"(b1));
}

// ---------------- f32x2 helpers ----------------
__device__ __forceinline__ void ffma2(ull &d, ull a, ull b) {
    asm("fma.rn.f32x2 %0, %1, %2, %0;" : "+l"(d) : "l"(a), "l"(b));
}
__device__ __forceinline__ ull pack2(float x, float y) {
    ull r; asm("mov.b64 %0, {%1, %2};" : "=l"(r) : "f"(x), "f"(y)); return r;
}
__device__ __forceinline__ void unpack2(ull v, float &x, float &y) {
    asm("mov.b64 {%0, %1}, %2;" : "=f"(x), "=f"(y) : "l"(v));
}

// fast exp on the fma/alu pipes
__device__ __forceinline__ float fexp_poly(float x) {
    float z = x * 1.4426950408889634f;
    z = fmaxf(z, -120.f);
    float m = z + 12582912.0f;
    int n = __float_as_int(m) - 0x4B400000;
    float f = z - (m - 12582912.0f);
    float p = 1.3333558e-3f;
    p = fmaf(p, f, 9.6181291e-3f);
    p = fmaf(p, f, 5.5504109e-2f);
    p = fmaf(p, f, 2.4022651e-1f);
    p = fmaf(p, f, 6.9314718e-1f);
    p = fmaf(p, f, 1.0f);
    float r = __int_as_float(__float_as_int(p) + (n << 23));
    return (x < -80.f) ? 0.f : r;
}

// ---------------- device scratch (pre-swizzled blocked layouts) ----------------
__device__ __align__(256) __nv_bfloat16 g_Qbh[MBT*Ss*HD];
__device__ __align__(256) __nv_bfloat16 g_Qbl[MBT*Ss*HD];
__device__ __align__(256) __nv_bfloat16 g_Kbh[MBT*Ss*HD];
__device__ __align__(256) __nv_bfloat16 g_Kbl[MBT*Ss*HD];
__device__ __align__(256) __nv_bfloat16 g_Vbh[MBT*Ss*HD];
__device__ __align__(256) __nv_bfloat16 g_Vbl[MBT*Ss*HD];
__device__ __align__(256) __nv_bfloat16 g_Xh[MROWS*Dm];
__device__ __align__(256) __nv_bfloat16 g_Xl[MROWS*Dm];
__device__ __align__(256) __nv_bfloat16 g_Wh[3*Dm*Dm];
__device__ __align__(256) __nv_bfloat16 g_Wl[3*Dm*Dm];
__device__ float g_Xbar[Bb*NBR*Dm];
__device__ float g_tcb[Bb*NBR];
__device__ float g_tcf[Bb*NBR];
__device__ float g_Qh[MBT*NBR*HD];
__device__ float g_Kh[MBT*NBR*HD];
__device__ float g_Vh[MBT*NBR*HD];
__device__ float g_ll[MBT*NBR*NBR];
__device__ float g_prior[MBT*NBR*NBR];
__device__ float g_rowmax[MBT*NBR];
__device__ float g_thresh[MBT];
__device__ int   g_cnt[MBT*NBR];
__device__ int   g_list[MBT*NBR*NBR];
__device__ float g_low_out[MBT*NBR*HD];
__device__ float g_low_norm[MBT*NBR];

__device__ __forceinline__ unsigned f2ord(float f) {
    unsigned u = __float_as_uint(f);
    return (u & 0x80000000u) ? ~u : (u | 0x80000000u);
}

// ---------------- kernel 0a: split X -> k-chunk-major swizzled bf16 hi/lo ----------------
__global__ void convX_kernel(const float* __restrict__ X)
{
    int idx = blockIdx.x*256 + threadIdx.x;
    int row = idx / 96, cidx = idx % 96;
    int kc = cidx >> 2, c4 = cidx & 3;
    const float* src = X + (size_t)row*Dm + cidx*8;
    float4 v0 = *(const float4*)src;
    float4 v1 = *(const float4*)(src + 4);
    float vf[8] = {v0.x, v0.y, v0.z, v0.w, v1.x, v1.y, v1.z, v1.w};
    __nv_bfloat16 h[8], l[8];
    #pragma unroll
    for (int j = 0; j < 8; j++) {
        h[j] = __float2bfloat16(vf[j]);
        l[j] = __float2bfloat16(vf[j] - __bfloat162float(h[j]));
    }
    size_t dst = ((size_t)kc*MROWS + row)*64 + ((c4 ^ ((row>>1)&3))<<4);
    *(uint4*)((char*)g_Xh + dst) = *(uint4*)h;
    *(uint4*)((char*)g_Xl + dst) = *(uint4*)l;
}

// ---------------- kernel 0b: split W -> k-chunk-major swizzled bf16 hi/lo ----------------
__global__ void convW_kernel(const float* __restrict__ Wq,
                             const float* __restrict__ Wk,
                             const float* __restrict__ Wv)
{
    int mat = blockIdx.y;
    const float* W = (mat == 0) ? Wq : (mat == 1) ? Wk : Wv;
    int idx = blockIdx.x*256 + threadIdx.x;
    int n = idx / 96, cidx = idx % 96;
    int kc = cidx >> 2, c4 = cidx & 3;
    const float* src = W + (size_t)n*Dm + cidx*8;
    float4 v0 = *(const float4*)src;
    float4 v1 = *(const float4*)(src + 4);
    float vf[8] = {v0.x, v0.y, v0.z, v0.w, v1.x, v1.y, v1.z, v1.w};
    __nv_bfloat16 h[8], l[8];
    #pragma unroll
    for (int j = 0; j < 8; j++) {
        h[j] = __float2bfloat16(vf[j]);
        l[j] = __float2bfloat16(vf[j] - __bfloat162float(h[j]));
    }
    size_t dst = (((size_t)mat*24 + kc)*Dm + n)*64 + ((c4 ^ ((n>>1)&3))<<4);
    *(uint4*)((char*)g_Wh + dst) = *(uint4*)h;
    *(uint4*)((char*)g_Wl + dst) = *(uint4*)l;
}

// ---------------- kernel 0c: masked block-mean of X ----------------
__global__ void xbar_kernel(const float* __restrict__ X, const float* __restrict__ mask)
{
    int bn = blockIdx.x;
    int bb = bn >> 7, n = bn & 127;
    int d = threadIdx.x;
    const float* mrow = mask + (size_t)bb*Ss + n*BLKSZ;
    float tc = 0.f;
    #pragma unroll
    for (int t = 0; t < BLKSZ; t++) tc += mrow[t];
    float denom = tc + 1e-6f;
    const float* xp = X + ((size_t)bb*Ss + n*BLKSZ)*Dm + d;
    float s = 0.f;
    #pragma unroll 4
    for (int t = 0; t < BLKSZ; t++) s += mrow[t]*xp[(size_t)t*Dm];
    g_Xbar[(size_t)bn*Dm + d] = s/denom;
    if (d == 0) { g_tcb[bn] = tc; g_tcf[bn] = tc/denom; }
}

// ---------------- kernel 1: QKV projection, bulk pipeline, 64x64 warp tiles ----------------
#define QSTG 49152
#define QMBAR (3*QSTG)
#define GEMM_SMEM (QMBAR + 64)

__global__ __launch_bounds__(256, 1) void qkv_mma_kernel(
    const float* __restrict__ mask,
    const float* __restrict__ bq, const float* __restrict__ bk, const float* __restrict__ bv)
{
    extern __shared__ __align__(128) char smem[];
    const uint32_t sb = smem_u32(smem);
    const int tid = threadIdx.x, lane = tid & 31, wid = tid >> 5;
    const int m0 = blockIdx.x * 128;
    const int tile = blockIdx.y;          // 0..8
    const int mat = tile / 3;
    const int n0 = (tile % 3) * 256;
    const int wm = wid & 1;               // m strip of 64
    const int wn = wid >> 1;              // n strip of 64

    const float* bias = (mat == 0) ? bq : (mat == 1) ? bk : bv;
    __nv_bfloat16* outH = (mat == 0) ? g_Qbh : (mat == 1) ? g_Kbh : g_Vbh;
    __nv_bfloat16* outL = (mat == 0) ? g_Qbl : (mat == 1) ? g_Kbl : g_Vbl;

    if (tid == 0) {
        MB_INIT(sb + QMBAR + 0, 1);
        MB_INIT(sb + QMBAR + 8, 1);
        MB_INIT(sb + QMBAR + 16, 1);
    }
    __syncthreads();

    float acc[4][8][4];
    #pragma unroll
    for (int a = 0; a < 4; a++)
        #pragma unroll
        for (int b = 0; b < 8; b++)
            #pragma unroll
            for (int c = 0; c < 4; c++) acc[a][b][c] = 0.f;

    #define QISSUE(s) do { if (tid == 0) { \
        const int _b = (s) % 3; \
        const uint32_t _bb = sb + _b*QSTG; \
        const uint32_t _mb = sb + QMBAR + _b*8; \
        MB_ARRIVE_TX(_mb, 49152); \
        BULK_G2S(_bb,         (const char*)g_Xh + ((size_t)(s)*MROWS + m0)*64, 8192, _mb); \
        BULK_G2S(_bb + 8192,  (const char*)g_Xl + ((size_t)(s)*MROWS + m0)*64, 8192, _mb); \
        BULK_G2S(_bb + 16384, (const char*)g_Wh + (((size_t)mat*24 + (s))*Dm + n0)*64, 16384, _mb); \
        BULK_G2S(_bb + 32768, (const char*)g_Wl + (((size_t)mat*24 + (s))*Dm + n0)*64, 16384, _mb); \
    } } while (0)

    QISSUE(0);
    QISSUE(1);

    for (int s = 0; s < 24; s++) {
        MB_WAIT(sb + QMBAR + (s % 3)*8, (s / 3) & 1);
        __syncthreads();
        if (s + 2 < 24) QISSUE(s + 2);
        const uint32_t base = sb + (s % 3)*QSTG;

        #pragma unroll
        for (int kk = 0; kk < 2; kk++) {
            uint32_t ah[4][4], al[4][4];
            #pragma unroll
            for (int mt = 0; mt < 4; mt++) {
                int row = wm*64 + mt*16 + (lane & 7) + ((lane >> 3) & 1)*8;
                int cell = kk*2 + (lane >> 4);
                uint32_t ad = base + row*64 + ((cell ^ ((row >> 1) & 3)) << 4);
                ldsm4(ah[mt][0], ah[mt][1], ah[mt][2], ah[mt][3], ad);
                ldsm4(al[mt][0], al[mt][1], al[mt][2], al[mt][3], ad + 8192);
            }
            #pragma unroll
            for (int np = 0; np < 4; np++) {
                int n = wn*64 + np*16 + (lane & 7) + ((lane >> 4) << 3);
                int cellB = kk*2 + ((lane >> 3) & 1);
                uint32_t bd = base + 16384 + n*64 + ((cellB ^ ((n >> 1) & 3)) << 4);
                uint32_t b0, b1, b2, b3, c0, c1, c2, c3;
                ldsm4(b0, b1, b2, b3, bd);
                ldsm4(c0, c1, c2, c3, bd + 16384);
                #pragma unroll
                for (int mt = 0; mt < 4; mt++) {
                    mma16816(acc[mt][np*2],   ah[mt][0], ah[mt][1], ah[mt][2], ah[mt][3], b0, b1);
                    mma16816(acc[mt][np*2+1], ah[mt][0], ah[mt][1], ah[mt][2], ah[mt][3], b2, b3);
                    mma16816(acc[mt][np*2],   al[mt][0], al[mt][1], al[mt][2], al[mt][3], b0, b1);
                    mma16816(acc[mt][np*2+1], al[mt][0], al[mt][1], al[mt][2], al[mt][3], b2, b3);
                    mma16816(acc[mt][np*2],   ah[mt][0], ah[mt][1], ah[mt][2], ah[mt][3], c0, c1);
                    mma16816(acc[mt][np*2+1], ah[mt][0], ah[mt][1], ah[mt][2], ah[mt][3], c2, c3);
                }
            }
        }
    }

    const int h = (n0 + wn*64) >> 6;
    const float* bp = bias + n0 + wn*64;
    float2 bias2[8];
    #pragma unroll
    for (int nt = 0; nt < 8; nt++) bias2[nt] = *(const float2*)(bp + nt*8 + (lane & 3)*2);

    #pragma unroll
    for (int mt = 0; mt < 4; mt++) {
        #pragma unroll
        for (int half = 0; half < 2; half++) {
            int m = m0 + wm*64 + mt*16 + (lane >> 2) + half*8;
            int bbm = m >> 12, sx = m & 4095;
            float mv = mask[(size_t)bbm*Ss + sx];
            int mb_ = bbm*Hh + h, kb = sx >> 5, r = sx & 31;
            size_t tb = ((size_t)(mb_*128 + kb)*32 + r)*64;
            #pragma unroll
            for (int nt = 0; nt < 8; nt++) {
                size_t off = tb + ((nt ^ (r & 7)) << 3) + (lane & 3)*2;
                float wx = (acc[mt][nt][half*2+0] + bias2[nt].x)*mv;
                float wy = (acc[mt][nt][half*2+1] + bias2[nt].y)*mv;
                __nv_bfloat162 hv = __floats2bfloat162_rn(wx, wy);
                float hx = __bfloat162float(__low2bfloat16(hv));
                float hy = __bfloat162float(__high2bfloat16(hv));
                __nv_bfloat162 lv = __floats2bfloat162_rn(wx - hx, wy - hy);
                *(__nv_bfloat162*)(outH + off) = hv;
                *(__nv_bfloat162*)(outL + off) = lv;
            }
        }
    }
}

// ---------------- kernel 1b: exact fp32 block-mean projection (f32x2) ----------------
__global__ __launch_bounds__(256) void hmean_gemm_kernel(
    const float* __restrict__ Wq, const float* __restrict__ Wk, const float* __restrict__ Wv,
    const float* __restrict__ bq, const float* __restrict__ bk, const float* __restrict__ bv)
{
    __shared__ float As[32][33];
    __shared__ float Bs[128][33];

    const int mat = blockIdx.z;
    const float* W = (mat == 0) ? Wq : (mat == 1) ? Wk : Wv;
    const float* bias = (mat == 0) ? bq : (mat == 1) ? bk : bv;
    float* out = (mat == 0) ? g_Qh : (mat == 1) ? g_Kh : g_Vh;

    const int tid = threadIdx.x;
    const int r0 = blockIdx.x * 32;
    const int e0 = blockIdx.y * 128;
    const int tn = tid >> 4;
    const int tm2 = tid & 15;

    ull acc2[8];
    #pragma unroll
    for (int j = 0; j < 8; j++) acc2[j] = 0ull;

    for (int k0 = 0; k0 < Dm; k0 += 32) {
        {
            int r = tid >> 3, kq = tid & 7;
            float4 v = *(const float4*)&g_Xbar[(size_t)(r0 + r)*Dm + k0 + kq*4];
            As[r][kq*4+0] = v.x; As[r][kq*4+1] = v.y; As[r][kq*4+2] = v.z; As[r][kq*4+3] = v.w;
        }
        #pragma unroll
        for (int t = 0; t < 4; t++) {
            int idx = tid + t*256;
            int r = idx >> 3, kq = idx & 7;
            float4 v = *(const float4*)&W[(size_t)(e0 + r)*Dm + k0 + kq*4];
            Bs[r][kq*4+0] = v.x; Bs[r][kq*4+1] = v.y; Bs[r][kq*4+2] = v.z; Bs[r][kq*4+3] = v.w;
        }
        __syncthreads();
        #pragma unroll 8
        for (int k = 0; k < 32; k++) {
            ull a2 = pack2(As[tm2*2][k], As[tm2*2+1][k]);
            #pragma unroll
            for (int j = 0; j < 8; j++) {
                float b = Bs[tn*8+j][k];
                ffma2(acc2[j], a2, pack2(b, b));
            }
        }
        __syncthreads();
    }

    #pragma unroll
    for (int j = 0; j < 8; j++) {
        float v0, v1;
        unpack2(acc2[j], v0, v1);
        int e = e0 + tn*8 + j;
        int hh = e >> 6, hd = e & 63;
        #pragma unroll
        for (int i = 0; i < 2; i++) {
            const int r = r0 + tm2*2 + i;
            const int bb2 = r >> 7, n = r & 127;
            const float tcf = g_tcf[r];
            out[(((size_t)(bb2*Hh + hh))*NBR + n)*HD + hd] = (i ? v1 : v0) + bias[e]*tcf;
        }
    }
}

// ---------------- kernel 3: low-res logits (16 q-rows per CTA) ----------------
__global__ __launch_bounds__(256) void lowlogit_kernel()
{
    const int mb = blockIdx.y, q0 = blockIdx.x*16;
    const int bb = mb / Hh;
    const int tid = threadIdx.x;
    __shared__ float Kt[64][129];
    __shared__ float Qhs[16][65];
    __shared__ float tcs[NBR];

    for (int i = tid; i < NBR*HD; i += 256) {
        int m = i >> 6, d = i & 63;
        Kt[d][m] = g_Kh[((size_t)mb*NBR + m)*HD + d];
    }
    for (int i = tid; i < 16*HD; i += 256) {
        int qq = i >> 6, d = i & 63;
        Qhs[qq][d] = g_Qh[((size_t)mb*NBR + q0 + qq)*HD + d];
    }
    if (tid < NBR) tcs[tid] = g_tcb[bb*NBR + tid];
    __syncthreads();

    const int q = tid >> 4, mg = tid & 15;
    float s[8];
    #pragma unroll
    for (int k = 0; k < 8; k++) s[k] = 0.f;
    for (int d = 0; d < HD; d++) {
        float qv = Qhs[q][d];
        const float* kr = &Kt[d][mg];
        #pragma unroll
        for (int k = 0; k < 8; k++) s[k] += qv*kr[16*k];
    }
    #pragma unroll
    for (int k = 0; k < 8; k++) s[k] *= 0.125f;

    float mx = s[0];
    #pragma unroll
    for (int k = 1; k < 8; k++) mx = fmaxf(mx, s[k]);
    #pragma unroll
    for (int off = 8; off >= 1; off >>= 1)
        mx = fmaxf(mx, __shfl_xor_sync(0xffffffffu, mx, off, 16));
    const int n = q0 + q;
    if (mg == 0) g_rowmax[mb*NBR + n] = mx;

    const float tcn = tcs[n];
    float* llr = g_ll + ((size_t)mb*NBR + n)*NBR;
    float* prr = g_prior + ((size_t)mb*NBR + n)*NBR;
    #pragma unroll
    for (int k = 0; k < 8; k++) {
        int m = mg + 16*k;
        float pe = (tcn*tcs[m] < 0.5f) ? 1.0f : 0.0f;
        float ll = s[k] - 1e4f*pe;
        float prior = ll - mx;
        int dif = n - m; if (dif < 0) dif = -dif;
        if (dif <= 1) prior += 5e3f;
        llr[m] = ll;
        prr[m] = prior;
    }
}

// ---------------- kernel 4+5 merged: radix threshold + deterministic select ----------------
#define TS_SMEM (NBR*NBR*4 + 256*4 + 16)
__global__ __launch_bounds__(256) void threshsel_kernel()
{
    extern __shared__ __align__(16) float ts_sm[];
    float* prs = ts_sm;
    unsigned* hist = (unsigned*)(ts_sm + NBR*NBR);
    unsigned* ctrl = hist + 256;

    const int mb = blockIdx.x;
    const int tid = threadIdx.x;
    const int lane = tid & 31;
    const float* pr = g_prior + (size_t)mb*NBR*NBR;
    for (int i = tid; i < NBR*NBR; i += 256) prs[i] = pr[i];
    if (tid == 0) { ctrl[0] = 0u; ctrl[1] = NUMBLK; }
    __syncthreads();

    for (int pass = 0; pass < 4; pass++) {
        int shift = 24 - pass*8;
        hist[tid] = 0u;
        __syncthreads();
        unsigned pref = ctrl[0];
        for (int i = tid; i < NBR*NBR; i += 256) {
            unsigned u = f2ord(prs[i]);
            bool ok = (pass == 0) ? true : (((u ^ pref) >> (shift + 8)) == 0u);
            unsigned bin = ok ? ((u >> shift) & 255u) : 0xFFFFFFFFu;
            unsigned mm = __match_any_sync(0xffffffffu, bin);
            if (bin != 0xFFFFFFFFu && (__ffs(mm) - 1) == lane)
                atomicAdd(&hist[bin], __popc(mm));
        }
        __syncthreads();
        if (tid == 0) {
            int k = (int)ctrl[1]; unsigned cum = 0u; int sel = 0;
            for (int bbin = 255; bbin >= 0; bbin--) {
                unsigned h = hist[bbin];
                if (cum + h >= (unsigned)k) { sel = bbin; break; }
                cum += h;
            }
            ctrl[1] = (unsigned)(k - (int)cum);
            ctrl[0] = pref | ((unsigned)sel << shift);
        }
        __syncthreads();
    }
    float t;
    {
        unsigned u = ctrl[0];
        unsigned raw = (u & 0x80000000u) ? (u & 0x7FFFFFFFu) : ~u;
        t = __uint_as_float(raw);
    }
    if (tid == 0) g_thresh[mb] = t;

    if (tid < 128) {
        const int n = tid;
        const float* prow = prs + n*NBR;
        int* lst = g_list + ((size_t)mb*NBR + n)*NBR;
        int c = 0;
        for (int m = 0; m < NBR; m++)
            if (prow[m] >= t) lst[c++] = m;
        g_cnt[mb*NBR + n] = c;
    }
}

// ---------------- kernel 7: low-res attention (16 n-rows per CTA) ----------------
__global__ __launch_bounds__(256) void lowres_kernel()
{
    const int mb = blockIdx.y, n0 = blockIdx.x*16;
    const int bb = mb / Hh;
    const int tid = threadIdx.x;
    __shared__ float4 V4[NBR][16];
    __shared__ float a_sh[16][129];
    __shared__ float tcs[NBR];

    for (int i = tid; i < NBR*16; i += 256) {
        int m = i >> 4, dg = i & 15;
        V4[m][dg] = *(const float4*)&g_Vh[((size_t)mb*NBR + m)*HD + dg*4];
    }
    if (tid < NBR) tcs[tid] = g_tcb[bb*NBR + tid];
    __syncthreads();

    const int nn = tid >> 4, mg = tid & 15;
    const int n = n0 + nn;
    const float rmv = g_rowmax[mb*NBR + n];
    const float t = g_thresh[mb];
    const float* llr = g_ll + ((size_t)mb*NBR + n)*NBR;
    const float* prr = g_prior + ((size_t)mb*NBR + n)*NBR;
    float psum = 0.f;
    #pragma unroll
    for (int k = 0; k < 8; k++) {
        int m = mg + 16*k;
        float sel = (prr[m] >= t) ? 1e4f : 0.f;
        float a = __expf(llr[m] - rmv - sel) * tcs[m];
        a_sh[nn][m] = a;
        psum += a;
    }
    #pragma unroll
    for (int off = 8; off >= 1; off >>= 1)
        psum += __shfl_xor_sync(0xffffffffu, psum, off, 16);
    if (mg == 0) g_low_norm[mb*NBR + n] = psum;
    __syncthreads();

    {
        const int dg = tid & 15;
        const float* ar = a_sh[tid >> 4];
        float4 acc = make_float4(0.f, 0.f, 0.f, 0.f);
        #pragma unroll 8
        for (int m = 0; m < NBR; m++) {
            float av = ar[m];
            float4 v = V4[m][dg];
            acc.x += av*v.x; acc.y += av*v.y; acc.z += av*v.z; acc.w += av*v.w;
        }
        *(float4*)&g_low_out[((size_t)mb*NBR + n0 + (tid >> 4))*HD + dg*4] = acc;
    }
}

// ---------------- kernel 6: high-res attention (register softmax state) + fused combine ----------------
#define SKH 0
#define SKL 8192
#define SVH 16384
#define SVL 24576
#define SQH 32768
#define SQL 36864
#define SMK 40960
#define SPH 41216
#define SPL 43776
#define SMAXP 46336
#define SSUMP 46848
#define SMBR 47360
#define HR_SMEM 47424

__global__ __launch_bounds__(128) void highres_kernel(const float* __restrict__ mask,
                                                      float* __restrict__ gout)
{
    __shared__ __align__(128) char sm[HR_SMEM];
    __shared__ float QM[32];
    __shared__ float LOWR[64];
    __shared__ float s_rmb, s_ln;
    const uint32_t sb = smem_u32(sm);
    const int mbn = blockIdx.x;
    const int mb = mbn >> 7, q = mbn & 127;
    const int bb = mb / Hh, hh = mb % Hh;
    const int tid = threadIdx.x;
    const int lane = tid & 31, w = tid >> 5;

    const int nb = g_cnt[mbn];
    const int* lst = g_list + (size_t)mbn*NBR;

    float* MAXP = (float*)(sm + SMAXP);
    float* SUMP = (float*)(sm + SSUMP);

    // per-thread softmax state for rows {lane>>2, +8, 16+lane>>2, +8}
    float rm_reg[4] = {-1e30f, -1e30f, -1e30f, -1e30f};
    float nrmp[4] = {0.f, 0.f, 0.f, 0.f};

    {
        size_t qtb = ((size_t)mb*128 + q)*4096;
        const uint4* qh = (const uint4*)((const char*)g_Qbh + qtb);
        const uint4* ql = (const uint4*)((const char*)g_Qbl + qtb);
        for (int i = tid; i < 256; i += 128) {
            ((uint4*)(sm + SQH))[i] = qh[i];
            ((uint4*)(sm + SQL))[i] = ql[i];
        }
    }
    if (tid == 0) { MB_INIT(sb + SMBR, 1); MB_INIT(sb + SMBR + 8, 1); }
    if (tid < 32) QM[tid] = mask[(size_t)bb*Ss + q*BLKSZ + tid];
    if (tid >= 64 && tid < 128) LOWR[tid - 64] = g_low_out[((size_t)mb*NBR + q)*HD + tid - 64];
    if (tid == 32) s_rmb = g_rowmax[mb*NBR + q];
    if (tid == 33) s_ln = g_low_norm[mb*NBR + q];
    __syncthreads();

    uint32_t aQh[2][4][4], aQl[2][4][4];
    #pragma unroll
    for (int mt = 0; mt < 2; mt++) {
        int row = mt*16 + (lane & 7) + ((lane >> 3) & 1)*8;
        #pragma unroll
        for (int ks = 0; ks < 4; ks++) {
            int cell = ks*2 + (lane >> 4);
            uint32_t ad = sb + SQH + row*128 + ((cell ^ (row & 7)) << 4);
            ldsm4(aQh[mt][ks][0], aQh[mt][ks][1], aQh[mt][ks][2], aQh[mt][ks][3], ad);
            ldsm4(aQl[mt][ks][0], aQl[mt][ks][1], aQl[mt][ks][2], aQl[mt][ks][3], ad + 4096);
        }
    }
    __syncthreads();

    float o[2][2][4];
    #pragma unroll
    for (int mt = 0; mt < 2; mt++)
        #pragma unroll
        for (int nt = 0; nt < 2; nt++)
            #pragma unroll
            for (int j = 0; j < 4; j++) o[mt][nt][j] = 0.f;

    #define HR_ISSUE(st, kb) do { if (tid == 0) { \
        uint32_t _mb = sb + SMBR + (st)*8; \
        MB_ARRIVE_TX(_mb, 16512); \
        size_t _tb = ((size_t)mb*128 + (kb))*4096; \
        BULK_G2S(sb + SKH + (st)*4096, (const char*)g_Kbh + _tb, 4096, _mb); \
        BULK_G2S(sb + SKL + (st)*4096, (const char*)g_Kbl + _tb, 4096, _mb); \
        BULK_G2S(sb + SVH + (st)*4096, (const char*)g_Vbh + _tb, 4096, _mb); \
        BULK_G2S(sb + SVL + (st)*4096, (const char*)g_Vbl + _tb, 4096, _mb); \
        BULK_G2S(sb + SMK + (st)*128, (const char*)(mask + (size_t)bb*Ss + (size_t)(kb)*BLKSZ), 128, _mb); \
    } } while (0)

    if (nb > 0) HR_ISSUE(0, lst[0]);

    for (int it = 0; it < nb; it++) {
        const int cur = it & 1;
        MB_WAIT(sb + SMBR + cur*8, (it >> 1) & 1);   // all threads wait; acquire orders data

        // ---- S = Qh*Kh + Qh*Kl + Ql*Kh ----
        float sacc[2][4];
        #pragma unroll
        for (int mt = 0; mt < 2; mt++)
            #pragma unroll
            for (int j = 0; j < 4; j++) sacc[mt][j] = 0.f;

        const uint32_t khb = sb + SKH + cur*4096;
        uint32_t kbh[4][2], kbl[4][2];
        #pragma unroll
        for (int ks = 0; ks < 4; ks++) {
            int kr = 8*w + (lane & 7);
            int cell = ks*2 + ((lane >> 3) & 1);
            uint32_t baddr = khb + kr*128 + ((cell ^ (kr & 7)) << 4);
            ldsm2(kbh[ks][0], kbh[ks][1], baddr);
            ldsm2(kbl[ks][0], kbl[ks][1], baddr + 8192);
        }
        #pragma unroll
        for (int ks = 0; ks < 4; ks++) {
            #pragma unroll
            for (int mt = 0; mt < 2; mt++) {
                mma16816(sacc[mt], aQh[mt][ks][0], aQh[mt][ks][1], aQh[mt][ks][2], aQh[mt][ks][3], kbh[ks][0], kbh[ks][1]);
                mma16816(sacc[mt], aQh[mt][ks][0], aQh[mt][ks][1], aQh[mt][ks][2], aQh[mt][ks][3], kbl[ks][0], kbl[ks][1]);
                mma16816(sacc[mt], aQl[mt][ks][0], aQl[mt][ks][1], aQl[mt][ks][2], aQl[mt][ks][3], kbh[ks][0], kbh[ks][1]);
            }
        }
        #pragma unroll
        for (int mt = 0; mt < 2; mt++)
            #pragma unroll
            for (int j = 0; j < 4; j++) sacc[mt][j] *= 0.125f;

        // per-warp partial row max to smem
        #pragma unroll
        for (int mt = 0; mt < 2; mt++) {
            float m1 = fmaxf(sacc[mt][0], sacc[mt][1]);
            float m2 = fmaxf(sacc[mt][2], sacc[mt][3]);
            m1 = fmaxf(m1, __shfl_xor_sync(0xffffffffu, m1, 1, 4));
            m1 = fmaxf(m1, __shfl_xor_sync(0xffffffffu, m1, 2, 4));
            m2 = fmaxf(m2, __shfl_xor_sync(0xffffffffu, m2, 1, 4));
            m2 = fmaxf(m2, __shfl_xor_sync(0xffffffffu, m2, 2, 4));
            if ((lane & 3) == 0) {
                int r1 = mt*16 + (lane >> 2);
                MAXP[r1*4 + w] = m1;
                MAXP[(r1+8)*4 + w] = m2;
            }
        }
        __syncthreads();   // sync1: MAXP complete; all prior AV (it-1) complete

        if (it + 1 < nb) HR_ISSUE((it+1) & 1, lst[it+1]);   // safe: all done reading that buffer

        // all threads redundantly reduce MAXP, update register rm/sc
        float sc_reg[4];
        #pragma unroll
        for (int i = 0; i < 4; i++) {
            int ri = (i >> 1)*16 + (i & 1)*8 + (lane >> 2);
            float tm = fmaxf(fmaxf(MAXP[ri*4], MAXP[ri*4+1]), fmaxf(MAXP[ri*4+2], MAXP[ri*4+3]));
            float nm = fmaxf(rm_reg[i], tm);
            sc_reg[i] = __expf(rm_reg[i] - nm);
            rm_reg[i] = nm;
        }

        const float kmv0 = ((const float*)(sm + SMK + cur*128))[8*w + (lane & 3)*2];
        const float kmv1 = ((const float*)(sm + SMK + cur*128))[8*w + (lane & 3)*2 + 1];
        const float pen0 = 1e4f*(1.f - kmv0), pen1 = 1e4f*(1.f - kmv1);
        const int colb = (8*w + (lane & 3)*2)*2;

        #pragma unroll
        for (int mt = 0; mt < 2; mt++) {
            int r1 = mt*16 + (lane >> 2), r2 = r1 + 8;
            float sc1 = sc_reg[mt*2], sc2 = sc_reg[mt*2+1];
            float rm1 = rm_reg[mt*2], rm2 = rm_reg[mt*2+1];
            #pragma unroll
            for (int nt = 0; nt < 2; nt++) {
                o[mt][nt][0] *= sc1; o[mt][nt][1] *= sc1;
                o[mt][nt][2] *= sc2; o[mt][nt][3] *= sc2;
            }
            float p00, p01, p10, p11;
            if (mt == 0) {
                p00 = __expf(sacc[mt][0] - rm1 - pen0);
                p01 = __expf(sacc[mt][1] - rm1 - pen1);
                p10 = __expf(sacc[mt][2] - rm2 - pen0);
                p11 = fexp_poly(sacc[mt][3] - rm2 - pen1);
            } else {
                p00 = __expf(sacc[mt][0] - rm1 - pen0);
                p01 = __expf(sacc[mt][1] - rm1 - pen1);
                p10 = fexp_poly(sacc[mt][2] - rm2 - pen0);
                p11 = fexp_poly(sacc[mt][3] - rm2 - pen1);
            }

            __nv_bfloat162 ph0 = __floats2bfloat162_rn(p00, p01);
            __nv_bfloat162 pl0 = __floats2bfloat162_rn(
                p00 - __bfloat162float(__low2bfloat16(ph0)),
                p01 - __bfloat162float(__high2bfloat16(ph0)));
            __nv_bfloat162 ph1 = __floats2bfloat162_rn(p10, p11);
            __nv_bfloat162 pl1 = __floats2bfloat162_rn(
                p10 - __bfloat162float(__low2bfloat16(ph1)),
                p11 - __bfloat162float(__high2bfloat16(ph1)));
            *(__nv_bfloat162*)(sm + SPH + r1*80 + colb) = ph0;
            *(__nv_bfloat162*)(sm + SPL + r1*80 + colb) = pl0;
            *(__nv_bfloat162*)(sm + SPH + r2*80 + colb) = ph1;
            *(__nv_bfloat162*)(sm + SPL + r2*80 + colb) = pl1;

            float s1 = p00 + p01, s2 = p10 + p11;
            s1 += __shfl_xor_sync(0xffffffffu, s1, 1, 4);
            s1 += __shfl_xor_sync(0xffffffffu, s1, 2, 4);
            s2 += __shfl_xor_sync(0xffffffffu, s2, 1, 4);
            s2 += __shfl_xor_sync(0xffffffffu, s2, 2, 4);
            nrmp[mt*2]   = nrmp[mt*2]*sc1 + s1;     // per-warp partial, register state
            nrmp[mt*2+1] = nrmp[mt*2+1]*sc2 + s2;
        }
        __syncthreads();   // sync2: P ready

        const uint32_t vhb = sb + SVH + cur*4096;
        #pragma unroll
        for (int ks = 0; ks < 2; ks++) {
            uint32_t aPh[2][4], aPl[2][4];
            #pragma unroll
            for (int mt = 0; mt < 2; mt++) {
                int row = mt*16 + (lane & 7) + ((lane >> 3) & 1)*8;
                uint32_t pad = sb + SPH + row*80 + (ks*2 + (lane >> 4))*16;
                ldsm4(aPh[mt][0], aPh[mt][1], aPh[mt][2], aPh[mt][3], pad);
                ldsm4(aPl[mt][0], aPl[mt][1], aPl[mt][2], aPl[mt][3], pad + (SPL - SPH));
            }
            int vrow = ks*16 + (lane & 7) + ((lane >> 3) & 1)*8;
            int vcell = 2*w + (lane >> 4);
            uint32_t vad = vhb + vrow*128 + ((vcell ^ (vrow & 7)) << 4);
            uint32_t bh0, bh1, bh2, bh3, bl0, bl1, bl2, bl3;
            ldsm4t(bh0, bh1, bh2, bh3, vad);
            ldsm4t(bl0, bl1, bl2, bl3, vad + 8192);
            #pragma unroll
            for (int mt = 0; mt < 2; mt++) {
                mma16816(o[mt][0], aPh[mt][0], aPh[mt][1], aPh[mt][2], aPh[mt][3], bh0, bh1);
                mma16816(o[mt][1], aPh[mt][0], aPh[mt][1], aPh[mt][2], aPh[mt][3], bh2, bh3);
                mma16816(o[mt][0], aPh[mt][0], aPh[mt][1], aPh[mt][2], aPh[mt][3], bl0, bl1);
                mma16816(o[mt][1], aPh[mt][0], aPh[mt][1], aPh[mt][2], aPh[mt][3], bl2, bl3);
                mma16816(o[mt][0], aPl[mt][0], aPl[mt][1], aPl[mt][2], aPl[mt][3], bh0, bh1);
                mma16816(o[mt][1], aPl[mt][0], aPl[mt][1], aPl[mt][2], aPl[mt][3], bh2, bh3);
            }
        }
        // no end barrier: next iter's sync1 gates all WAR hazards
    }

    // combine NRM partials across warps
    #pragma unroll
    for (int i = 0; i < 4; i++) {
        int ri = (i >> 1)*16 + (i & 1)*8 + (lane >> 2);
        if ((lane & 3) == 0) SUMP[ri*4 + w] = nrmp[i];
    }
    __syncthreads();
    float nrm_tot[4];
    #pragma unroll
    for (int i = 0; i < 4; i++) {
        int ri = (i >> 1)*16 + (i & 1)*8 + (lane >> 2);
        nrm_tot[i] = SUMP[ri*4] + SUMP[ri*4+1] + SUMP[ri*4+2] + SUMP[ri*4+3];
    }

    // ---- fused combine epilogue ----
    const float rmb = s_rmb, lnv = s_ln;
    #pragma unroll
    for (int mt = 0; mt < 2; mt++) {
        int r1 = mt*16 + (lane >> 2), r2 = r1 + 8;
        float mx1 = fmaxf(rm_reg[mt*2], -1e6f), mx2 = fmaxf(rm_reg[mt*2+1], -1e6f);
        float lcl1 = (rmb - mx1)*QM[r1], lcl2 = (rmb - mx2)*QM[r2];
        float lc1 = __expf(fminf(lcl1, 0.f)), hc1 = __expf(-fmaxf(lcl1, 0.f));
        float lc2 = __expf(fminf(lcl2, 0.f)), hc2 = __expf(-fmaxf(lcl2, 0.f));
        float inv1 = 1.f/(nrm_tot[mt*2]*hc1 + lnv*lc1 + 1e-6f);
        float inv2 = 1.f/(nrm_tot[mt*2+1]*hc2 + lnv*lc2 + 1e-6f);
        float* op1 = gout + ((size_t)bb*Ss + q*BLKSZ + r1)*Dm + hh*HD;
        float* op2 = gout + ((size_t)bb*Ss + q*BLKSZ + r2)*Dm + hh*HD;
        #pragma unroll
        for (int nt = 0; nt < 2; nt++) {
            int col = 16*w + nt*8 + (lane & 3)*2;
            float2 w1, w2;
            w1.x = (o[mt][nt][0]*hc1 + LOWR[col]*lc1)*inv1;
            w1.y = (o[mt][nt][1]*hc1 + LOWR[col+1]*lc1)*inv1;
            w2.x = (o[mt][nt][2]*hc2 + LOWR[col]*lc2)*inv2;
            w2.y = (o[mt][nt][3]*hc2 + LOWR[col+1]*lc2)*inv2;
            *(float2*)(op1 + col) = w1;
            *(float2*)(op2 + col) = w2;
        }
    }
}

// ---------------- launch ----------------
extern "C" void kernel_launch(void* const* d_in, const int* in_sizes, int n_in,
                              void* d_out, int out_size)
{
    const float* X    = (const float*)d_in[0];
    const float* mask = (const float*)d_in[1];
    const float* Wq   = (const float*)d_in[2];
    const float* bq   = (const float*)d_in[3];
    const float* Wk   = (const float*)d_in[4];
    const float* bk   = (const float*)d_in[5];
    const float* Wv   = (const float*)d_in[6];
    const float* bv   = (const float*)d_in[7];
    float* out = (float*)d_out;

    cudaFuncSetAttribute(qkv_mma_kernel, cudaFuncAttributeMaxDynamicSharedMemorySize, GEMM_SMEM);
    cudaFuncSetAttribute(threshsel_kernel, cudaFuncAttributeMaxDynamicSharedMemorySize, TS_SMEM);

    convX_kernel<<<MROWS*96/256, 256>>>(X);                        // 1
    convW_kernel<<<dim3(Dm*96/256, 3), 256>>>(Wq, Wk, Wv);         // 2
    xbar_kernel<<<Bb*NBR, Dm>>>(X, mask);                          // 3
    qkv_mma_kernel<<<dim3(MROWS/128, 9), 256, GEMM_SMEM>>>(mask, bq, bk, bv);  // 4 (profiled slot)
    hmean_gemm_kernel<<<dim3(8, 6, 3), 256>>>(Wq, Wk, Wv, bq, bk, bv);         // 5
    lowlogit_kernel<<<dim3(8, MBT), 256>>>();                      // 6
    threshsel_kernel<<<MBT, 256, TS_SMEM>>>();                     // 7
    lowres_kernel<<<dim3(8, MBT), 256>>>();                        // 8
    highres_kernel<<<MBT*NBR, 128>>>(mask, out);                   // 9 (writes final out)
}

// round 14
// speedup vs baseline: 1.0409x; 1.0409x over previous
#include <cuda_runtime.h>
#include <cuda_bf16.h>
#include <cstdint>

// ---------------- problem constants ----------------
#define Bb 2
#define Ss 4096
#define Dm 768
#define Hh 12
#define HD 64
#define BLKSZ 32
#define NBR 128
#define NUMBLK 1024
#define MBT (Bb*Hh)        // 24
#define MROWS (Bb*Ss)      // 8192

typedef unsigned long long ull;

__device__ __forceinline__ uint32_t smem_u32(const void* p) {
    uint32_t a;
    asm("{ .reg .u64 t; cvta.to.shared.u64 t, %1; cvt.u32.u64 %0, t; }" : "=r"(a) : "l"(p));
    return a;
}

// ---------------- mbarrier + bulk-copy helpers ----------------
#define MB_INIT(mb, c) \
    asm volatile("mbarrier.init.shared.b64 [%0], %1;" :: "r"((uint32_t)(mb)), "r"((uint32_t)(c)) : "memory")
#define MB_ARRIVE_TX(mb, bytes) \
    asm volatile("mbarrier.arrive.expect_tx.shared.b64 _, [%0], %1;" :: "r"((uint32_t)(mb)), "r"((uint32_t)(bytes)) : "memory")
#define BULK_G2S(dst, src, size, mb) \
    asm volatile("cp.async.bulk.shared::cluster.global.mbarrier::complete_tx::bytes [%0], [%1], %2, [%3];" \
        :: "r"((uint32_t)(dst)), "l"(src), "r"((uint32_t)(size)), "r"((uint32_t)(mb)) : "memory")
#define MB_WAIT(mb, ph) do { \
    uint32_t _m = (uint32_t)(mb); uint32_t _p = (uint32_t)(ph); uint32_t _d; \
    asm volatile("{\n\t.reg .pred p;\n\tmbarrier.try_wait.parity.acquire.cta.shared::cta.b64 p, [%1], %2;\n\tselp.b32 %0, 1, 0, p;\n\t}" \
        : "=r"(_d) : "r"(_m), "r"(_p) : "memory"); \
    if (!_d) { \
        asm volatile("{\n\t.reg .pred P1;\n\tWL_%=:\n\tmbarrier.try_wait.parity.acquire.cta.shared::cta.b64 P1, [%0], %1, 0x989680;\n\t@P1 bra.uni WD_%=;\n\tbra.uni WL_%=;\n\tWD_%=:\n\t}" \
            :: "r"(_m), "r"(_p) : "memory"); \
    } } while (0)

// ---------------- mma.sync helpers ----------------
__device__ __forceinline__ void ldsm4(uint32_t &r0, uint32_t &r1, uint32_t &r2, uint32_t &r3, uint32_t addr) {
    asm volatile("ldmatrix.sync.aligned.m8n8.x4.shared.b16 {%0,%1,%2,%3}, [%4];"
        : "=r"(r0), "=r"(r1), "=r"(r2), "=r"(r3) : "r"(addr));
}
__device__ __forceinline__ void ldsm2(uint32_t &r0, uint32_t &r1, uint32_t addr) {
    asm volatile("ldmatrix.sync.aligned.m8n8.x2.shared.b16 {%0,%1}, [%2];"
        : "=r"(r0), "=r"(r1) : "r"(addr));
}
__device__ __forceinline__ void ldsm4t(uint32_t &r0, uint32_t &r1, uint32_t &r2, uint32_t &r3, uint32_t addr) {
    asm volatile("ldmatrix.sync.aligned.m8n8.x4.trans.shared.b16 {%0,%1,%2,%3}, [%4];"
        : "=r"(r0), "=r"(r1), "=r"(r2), "=r"(r3) : "r"(addr));
}
__device__ __forceinline__ void mma16816(float* c,
    uint32_t a0, uint32_t a1, uint32_t a2, uint32_t a3, uint32_t b0, uint32_t b1) {
    asm volatile("mma.sync.aligned.m16n8k16.row.col.f32.bf16.bf16.f32 "
        "{%0,%1,%2,%3}, {%4,%5,%6,%7}, {%8,%9}, {%0,%1,%2,%3};"
        : "+f"(c[0]), "+f"(c[1]), "+f"(c[2]), "+f"(c[3])
        : "r"(a0), "r"(a1), "r"(a2), "r"(a3), "r"(b0), "r"(b1));
}

// ---------------- f32x2 helpers ----------------
__device__ __forceinline__ void ffma2(ull &d, ull a, ull b) {
    asm("fma.rn.f32x2 %0, %1, %2, %0;" : "+l"(d) : "l"(a), "l"(b));
}
__device__ __forceinline__ ull pack2(float x, float y) {
    ull r; asm("mov.b64 %0, {%1, %2};" : "=l"(r) : "f"(x), "f"(y)); return r;
}
__device__ __forceinline__ void unpack2(ull v, float &x, float &y) {
    asm("mov.b64 {%0, %1}, %2;" : "=f"(x), "=f"(y) : "l"(v));
}

// fast exp on the fma/alu pipes
__device__ __forceinline__ float fexp_poly(float x) {
    float z = x * 1.4426950408889634f;
    z = fmaxf(z, -120.f);
    float m = z + 12582912.0f;
    int n = __float_as_int(m) - 0x4B400000;
    float f = z - (m - 12582912.0f);
    float p = 1.3333558e-3f;
    p = fmaf(p, f, 9.6181291e-3f);
    p = fmaf(p, f, 5.5504109e-2f);
    p = fmaf(p, f, 2.4022651e-1f);
    p = fmaf(p, f, 6.9314718e-1f);
    p = fmaf(p, f, 1.0f);
    float r = __int_as_float(__float_as_int(p) + (n << 23));
    return (x < -80.f) ? 0.f : r;
}

// ---------------- device scratch (pre-swizzled blocked layouts) ----------------
__device__ __align__(256) __nv_bfloat16 g_Qbh[MBT*Ss*HD];
__device__ __align__(256) __nv_bfloat16 g_Qbl[MBT*Ss*HD];
__device__ __align__(256) __nv_bfloat16 g_Kbh[MBT*Ss*HD];
__device__ __align__(256) __nv_bfloat16 g_Kbl[MBT*Ss*HD];
__device__ __align__(256) __nv_bfloat16 g_Vbh[MBT*Ss*HD];
__device__ __align__(256) __nv_bfloat16 g_Vbl[MBT*Ss*HD];
__device__ __align__(256) __nv_bfloat16 g_Xh[MROWS*Dm];
__device__ __align__(256) __nv_bfloat16 g_Xl[MROWS*Dm];
__device__ __align__(256) __nv_bfloat16 g_Wh[3*Dm*Dm];
__device__ __align__(256) __nv_bfloat16 g_Wl[3*Dm*Dm];
__device__ float g_Xbar[Bb*NBR*Dm];
__device__ float g_tcb[Bb*NBR];
__device__ float g_tcf[Bb*NBR];
__device__ float g_Qh[MBT*NBR*HD];
__device__ float g_Kh[MBT*NBR*HD];
__device__ float g_Vh[MBT*NBR*HD];
__device__ float g_ll[MBT*NBR*NBR];
__device__ float g_prior[MBT*NBR*NBR];
__device__ float g_rowmax[MBT*NBR];
__device__ float g_thresh[MBT];
__device__ int   g_cnt[MBT*NBR];
__device__ int   g_list[MBT*NBR*NBR];
__device__ float g_low_out[MBT*NBR*HD];
__device__ float g_low_norm[MBT*NBR];

__device__ __forceinline__ unsigned f2ord(float f) {
    unsigned u = __float_as_uint(f);
    return (u & 0x80000000u) ? ~u : (u | 0x80000000u);
}

// ---------------- kernel 0a: split X -> k-chunk-major swizzled bf16 hi/lo ----------------
__global__ void convX_kernel(const float* __restrict__ X)
{
    int idx = blockIdx.x*256 + threadIdx.x;
    int row = idx / 96, cidx = idx % 96;
    int kc = cidx >> 2, c4 = cidx & 3;
    const float* src = X + (size_t)row*Dm + cidx*8;
    float4 v0 = *(const float4*)src;
    float4 v1 = *(const float4*)(src + 4);
    float vf[8] = {v0.x, v0.y, v0.z, v0.w, v1.x, v1.y, v1.z, v1.w};
    __nv_bfloat16 h[8], l[8];
    #pragma unroll
    for (int j = 0; j < 8; j++) {
        h[j] = __float2bfloat16(vf[j]);
        l[j] = __float2bfloat16(vf[j] - __bfloat162float(h[j]));
    }
    size_t dst = ((size_t)kc*MROWS + row)*64 + ((c4 ^ ((row>>1)&3))<<4);
    *(uint4*)((char*)g_Xh + dst) = *(uint4*)h;
    *(uint4*)((char*)g_Xl + dst) = *(uint4*)l;
}

// ---------------- kernel 0b: split W -> k-chunk-major swizzled bf16 hi/lo ----------------
__global__ void convW_kernel(const float* __restrict__ Wq,
                             const float* __restrict__ Wk,
                             const float* __restrict__ Wv)
{
    int mat = blockIdx.y;
    const float* W = (mat == 0) ? Wq : (mat == 1) ? Wk : Wv;
    int idx = blockIdx.x*256 + threadIdx.x;
    int n = idx / 96, cidx = idx % 96;
    int kc = cidx >> 2, c4 = cidx & 3;
    const float* src = W + (size_t)n*Dm + cidx*8;
    float4 v0 = *(const float4*)src;
    float4 v1 = *(const float4*)(src + 4);
    float vf[8] = {v0.x, v0.y, v0.z, v0.w, v1.x, v1.y, v1.z, v1.w};
    __nv_bfloat16 h[8], l[8];
    #pragma unroll
    for (int j = 0; j < 8; j++) {
        h[j] = __float2bfloat16(vf[j]);
        l[j] = __float2bfloat16(vf[j] - __bfloat162float(h[j]));
    }
    size_t dst = (((size_t)mat*24 + kc)*Dm + n)*64 + ((c4 ^ ((n>>1)&3))<<4);
    *(uint4*)((char*)g_Wh + dst) = *(uint4*)h;
    *(uint4*)((char*)g_Wl + dst) = *(uint4*)l;
}

// ---------------- kernel 0c: masked block-mean of X ----------------
__global__ void xbar_kernel(const float* __restrict__ X, const float* __restrict__ mask)
{
    int bn = blockIdx.x;
    int bb = bn >> 7, n = bn & 127;
    int d = threadIdx.x;
    const float* mrow = mask + (size_t)bb*Ss + n*BLKSZ;
    float tc = 0.f;
    #pragma unroll
    for (int t = 0; t < BLKSZ; t++) tc += mrow[t];
    float denom = tc + 1e-6f;
    const float* xp = X + ((size_t)bb*Ss + n*BLKSZ)*Dm + d;
    float s = 0.f;
    #pragma unroll 4
    for (int t = 0; t < BLKSZ; t++) s += mrow[t]*xp[(size_t)t*Dm];
    g_Xbar[(size_t)bn*Dm + d] = s/denom;
    if (d == 0) { g_tcb[bn] = tc; g_tcf[bn] = tc/denom; }
}

// ---------------- kernel 1: QKV projection, bulk pipeline, 64x64 warp tiles (R13, kept) ----------------
#define QSTG 49152
#define QMBAR (3*QSTG)
#define GEMM_SMEM (QMBAR + 64)

__global__ __launch_bounds__(256, 1) void qkv_mma_kernel(
    const float* __restrict__ mask,
    const float* __restrict__ bq, const float* __restrict__ bk, const float* __restrict__ bv)
{
    extern __shared__ __align__(128) char smem[];
    const uint32_t sb = smem_u32(smem);
    const int tid = threadIdx.x, lane = tid & 31, wid = tid >> 5;
    const int m0 = blockIdx.x * 128;
    const int tile = blockIdx.y;          // 0..8
    const int mat = tile / 3;
    const int n0 = (tile % 3) * 256;
    const int wm = wid & 1;               // m strip of 64
    const int wn = wid >> 1;              // n strip of 64

    const float* bias = (mat == 0) ? bq : (mat == 1) ? bk : bv;
    __nv_bfloat16* outH = (mat == 0) ? g_Qbh : (mat == 1) ? g_Kbh : g_Vbh;
    __nv_bfloat16* outL = (mat == 0) ? g_Qbl : (mat == 1) ? g_Kbl : g_Vbl;

    if (tid == 0) {
        MB_INIT(sb + QMBAR + 0, 1);
        MB_INIT(sb + QMBAR + 8, 1);
        MB_INIT(sb + QMBAR + 16, 1);
    }
    __syncthreads();

    float acc[4][8][4];
    #pragma unroll
    for (int a = 0; a < 4; a++)
        #pragma unroll
        for (int b = 0; b < 8; b++)
            #pragma unroll
            for (int c = 0; c < 4; c++) acc[a][b][c] = 0.f;

    #define QISSUE(s) do { if (tid == 0) { \
        const int _b = (s) % 3; \
        const uint32_t _bb = sb + _b*QSTG; \
        const uint32_t _mb = sb + QMBAR + _b*8; \
        MB_ARRIVE_TX(_mb, 49152); \
        BULK_G2S(_bb,         (const char*)g_Xh + ((size_t)(s)*MROWS + m0)*64, 8192, _mb); \
        BULK_G2S(_bb + 8192,  (const char*)g_Xl + ((size_t)(s)*MROWS + m0)*64, 8192, _mb); \
        BULK_G2S(_bb + 16384, (const char*)g_Wh + (((size_t)mat*24 + (s))*Dm + n0)*64, 16384, _mb); \
        BULK_G2S(_bb + 32768, (const char*)g_Wl + (((size_t)mat*24 + (s))*Dm + n0)*64, 16384, _mb); \
    } } while (0)

    QISSUE(0);
    QISSUE(1);

    for (int s = 0; s < 24; s++) {
        MB_WAIT(sb + QMBAR + (s % 3)*8, (s / 3) & 1);
        __syncthreads();
        if (s + 2 < 24) QISSUE(s + 2);
        const uint32_t base = sb + (s % 3)*QSTG;

        #pragma unroll
        for (int kk = 0; kk < 2; kk++) {
            uint32_t ah[4][4], al[4][4];
            #pragma unroll
            for (int mt = 0; mt < 4; mt++) {
                int row = wm*64 + mt*16 + (lane & 7) + ((lane >> 3) & 1)*8;
                int cell = kk*2 + (lane >> 4);
                uint32_t ad = base + row*64 + ((cell ^ ((row >> 1) & 3)) << 4);
                ldsm4(ah[mt][0], ah[mt][1], ah[mt][2], ah[mt][3], ad);
                ldsm4(al[mt][0], al[mt][1], al[mt][2], al[mt][3], ad + 8192);
            }
            #pragma unroll
            for (int np = 0; np < 4; np++) {
                int n = wn*64 + np*16 + (lane & 7) + ((lane >> 4) << 3);
                int cellB = kk*2 + ((lane >> 3) & 1);
                uint32_t bd = base + 16384 + n*64 + ((cellB ^ ((n >> 1) & 3)) << 4);
                uint32_t b0, b1, b2, b3, c0, c1, c2, c3;
                ldsm4(b0, b1, b2, b3, bd);
                ldsm4(c0, c1, c2, c3, bd + 16384);
                #pragma unroll
                for (int mt = 0; mt < 4; mt++) {
                    mma16816(acc[mt][np*2],   ah[mt][0], ah[mt][1], ah[mt][2], ah[mt][3], b0, b1);
                    mma16816(acc[mt][np*2+1], ah[mt][0], ah[mt][1], ah[mt][2], ah[mt][3], b2, b3);
                    mma16816(acc[mt][np*2],   al[mt][0], al[mt][1], al[mt][2], al[mt][3], b0, b1);
                    mma16816(acc[mt][np*2+1], al[mt][0], al[mt][1], al[mt][2], al[mt][3], b2, b3);
                    mma16816(acc[mt][np*2],   ah[mt][0], ah[mt][1], ah[mt][2], ah[mt][3], c0, c1);
                    mma16816(acc[mt][np*2+1], ah[mt][0], ah[mt][1], ah[mt][2], ah[mt][3], c2, c3);
                }
            }
        }
    }

    const int h = (n0 + wn*64) >> 6;
    const float* bp = bias + n0 + wn*64;
    float2 bias2[8];
    #pragma unroll
    for (int nt = 0; nt < 8; nt++) bias2[nt] = *(const float2*)(bp + nt*8 + (lane & 3)*2);

    #pragma unroll
    for (int mt = 0; mt < 4; mt++) {
        #pragma unroll
        for (int half = 0; half < 2; half++) {
            int m = m0 + wm*64 + mt*16 + (lane >> 2) + half*8;
            int bbm = m >> 12, sx = m & 4095;
            float mv = mask[(size_t)bbm*Ss + sx];
            int mb_ = bbm*Hh + h, kb = sx >> 5, r = sx & 31;
            size_t tb = ((size_t)(mb_*128 + kb)*32 + r)*64;
            #pragma unroll
            for (int nt = 0; nt < 8; nt++) {
                size_t off = tb + ((nt ^ (r & 7)) << 3) + (lane & 3)*2;
                float wx = (acc[mt][nt][half*2+0] + bias2[nt].x)*mv;
                float wy = (acc[mt][nt][half*2+1] + bias2[nt].y)*mv;
                __nv_bfloat162 hv = __floats2bfloat162_rn(wx, wy);
                float hx = __bfloat162float(__low2bfloat16(hv));
                float hy = __bfloat162float(__high2bfloat16(hv));
                __nv_bfloat162 lv = __floats2bfloat162_rn(wx - hx, wy - hy);
                *(__nv_bfloat162*)(outH + off) = hv;
                *(__nv_bfloat162*)(outL + off) = lv;
            }
        }
    }
}

// ---------------- kernel 1b: exact fp32 block-mean projection (f32x2) ----------------
__global__ __launch_bounds__(256) void hmean_gemm_kernel(
    const float* __restrict__ Wq, const float* __restrict__ Wk, const float* __restrict__ Wv,
    const float* __restrict__ bq, const float* __restrict__ bk, const float* __restrict__ bv)
{
    __shared__ float As[32][33];
    __shared__ float Bs[128][33];

    const int mat = blockIdx.z;
    const float* W = (mat == 0) ? Wq : (mat == 1) ? Wk : Wv;
    const float* bias = (mat == 0) ? bq : (mat == 1) ? bk : bv;
    float* out = (mat == 0) ? g_Qh : (mat == 1) ? g_Kh : g_Vh;

    const int tid = threadIdx.x;
    const int r0 = blockIdx.x * 32;
    const int e0 = blockIdx.y * 128;
    const int tn = tid >> 4;
    const int tm2 = tid & 15;

    ull acc2[8];
    #pragma unroll
    for (int j = 0; j < 8; j++) acc2[j] = 0ull;

    for (int k0 = 0; k0 < Dm; k0 += 32) {
        {
            int r = tid >> 3, kq = tid & 7;
            float4 v = *(const float4*)&g_Xbar[(size_t)(r0 + r)*Dm + k0 + kq*4];
            As[r][kq*4+0] = v.x; As[r][kq*4+1] = v.y; As[r][kq*4+2] = v.z; As[r][kq*4+3] = v.w;
        }
        #pragma unroll
        for (int t = 0; t < 4; t++) {
            int idx = tid + t*256;
            int r = idx >> 3, kq = idx & 7;
            float4 v = *(const float4*)&W[(size_t)(e0 + r)*Dm + k0 + kq*4];
            Bs[r][kq*4+0] = v.x; Bs[r][kq*4+1] = v.y; Bs[r][kq*4+2] = v.z; Bs[r][kq*4+3] = v.w;
        }
        __syncthreads();
        #pragma unroll 8
        for (int k = 0; k < 32; k++) {
            ull a2 = pack2(As[tm2*2][k], As[tm2*2+1][k]);
            #pragma unroll
            for (int j = 0; j < 8; j++) {
                float b = Bs[tn*8+j][k];
                ffma2(acc2[j], a2, pack2(b, b));
            }
        }
        __syncthreads();
    }

    #pragma unroll
    for (int j = 0; j < 8; j++) {
        float v0, v1;
        unpack2(acc2[j], v0, v1);
        int e = e0 + tn*8 + j;
        int hh = e >> 6, hd = e & 63;
        #pragma unroll
        for (int i = 0; i < 2; i++) {
            const int r = r0 + tm2*2 + i;
            const int bb2 = r >> 7, n = r & 127;
            const float tcf = g_tcf[r];
            out[(((size_t)(bb2*Hh + hh))*NBR + n)*HD + hd] = (i ? v1 : v0) + bias[e]*tcf;
        }
    }
}

// ---------------- kernel 3: low-res logits (16 q-rows per CTA) ----------------
__global__ __launch_bounds__(256) void lowlogit_kernel()
{
    const int mb = blockIdx.y, q0 = blockIdx.x*16;
    const int bb = mb / Hh;
    const int tid = threadIdx.x;
    __shared__ float Kt[64][129];
    __shared__ float Qhs[16][65];
    __shared__ float tcs[NBR];

    for (int i = tid; i < NBR*HD; i += 256) {
        int m = i >> 6, d = i & 63;
        Kt[d][m] = g_Kh[((size_t)mb*NBR + m)*HD + d];
    }
    for (int i = tid; i < 16*HD; i += 256) {
        int qq = i >> 6, d = i & 63;
        Qhs[qq][d] = g_Qh[((size_t)mb*NBR + q0 + qq)*HD + d];
    }
    if (tid < NBR) tcs[tid] = g_tcb[bb*NBR + tid];
    __syncthreads();

    const int q = tid >> 4, mg = tid & 15;
    float s[8];
    #pragma unroll
    for (int k = 0; k < 8; k++) s[k] = 0.f;
    for (int d = 0; d < HD; d++) {
        float qv = Qhs[q][d];
        const float* kr = &Kt[d][mg];
        #pragma unroll
        for (int k = 0; k < 8; k++) s[k] += qv*kr[16*k];
    }
    #pragma unroll
    for (int k = 0; k < 8; k++) s[k] *= 0.125f;

    float mx = s[0];
    #pragma unroll
    for (int k = 1; k < 8; k++) mx = fmaxf(mx, s[k]);
    #pragma unroll
    for (int off = 8; off >= 1; off >>= 1)
        mx = fmaxf(mx, __shfl_xor_sync(0xffffffffu, mx, off, 16));
    const int n = q0 + q;
    if (mg == 0) g_rowmax[mb*NBR + n] = mx;

    const float tcn = tcs[n];
    float* llr = g_ll + ((size_t)mb*NBR + n)*NBR;
    float* prr = g_prior + ((size_t)mb*NBR + n)*NBR;
    #pragma unroll
    for (int k = 0; k < 8; k++) {
        int m = mg + 16*k;
        float pe = (tcn*tcs[m] < 0.5f) ? 1.0f : 0.0f;
        float ll = s[k] - 1e4f*pe;
        float prior = ll - mx;
        int dif = n - m; if (dif < 0) dif = -dif;
        if (dif <= 1) prior += 5e3f;
        llr[m] = ll;
        prr[m] = prior;
    }
}

// ---------------- kernel 4+5 merged: radix threshold + deterministic select ----------------
#define TS_SMEM (NBR*NBR*4 + 256*4 + 16)
__global__ __launch_bounds__(256) void threshsel_kernel()
{
    extern __shared__ __align__(16) float ts_sm[];
    float* prs = ts_sm;
    unsigned* hist = (unsigned*)(ts_sm + NBR*NBR);
    unsigned* ctrl = hist + 256;

    const int mb = blockIdx.x;
    const int tid = threadIdx.x;
    const int lane = tid & 31;
    const float* pr = g_prior + (size_t)mb*NBR*NBR;
    for (int i = tid; i < NBR*NBR; i += 256) prs[i] = pr[i];
    if (tid == 0) { ctrl[0] = 0u; ctrl[1] = NUMBLK; }
    __syncthreads();

    for (int pass = 0; pass < 4; pass++) {
        int shift = 24 - pass*8;
        hist[tid] = 0u;
        __syncthreads();
        unsigned pref = ctrl[0];
        for (int i = tid; i < NBR*NBR; i += 256) {
            unsigned u = f2ord(prs[i]);
            bool ok = (pass == 0) ? true : (((u ^ pref) >> (shift + 8)) == 0u);
            unsigned bin = ok ? ((u >> shift) & 255u) : 0xFFFFFFFFu;
            unsigned mm = __match_any_sync(0xffffffffu, bin);
            if (bin != 0xFFFFFFFFu && (__ffs(mm) - 1) == lane)
                atomicAdd(&hist[bin], __popc(mm));
        }
        __syncthreads();
        if (tid == 0) {
            int k = (int)ctrl[1]; unsigned cum = 0u; int sel = 0;
            for (int bbin = 255; bbin >= 0; bbin--) {
                unsigned h = hist[bbin];
                if (cum + h >= (unsigned)k) { sel = bbin; break; }
                cum += h;
            }
            ctrl[1] = (unsigned)(k - (int)cum);
            ctrl[0] = pref | ((unsigned)sel << shift);
        }
        __syncthreads();
    }
    float t;
    {
        unsigned u = ctrl[0];
        unsigned raw = (u & 0x80000000u) ? (u & 0x7FFFFFFFu) : ~u;
        t = __uint_as_float(raw);
    }
    if (tid == 0) g_thresh[mb] = t;

    if (tid < 128) {
        const int n = tid;
        const float* prow = prs + n*NBR;
        int* lst = g_list + ((size_t)mb*NBR + n)*NBR;
        int c = 0;
        for (int m = 0; m < NBR; m++)
            if (prow[m] >= t) lst[c++] = m;
        g_cnt[mb*NBR + n] = c;
    }
}

// ---------------- kernel 7: low-res attention (16 n-rows per CTA) ----------------
__global__ __launch_bounds__(256) void lowres_kernel()
{
    const int mb = blockIdx.y, n0 = blockIdx.x*16;
    const int bb = mb / Hh;
    const int tid = threadIdx.x;
    __shared__ float4 V4[NBR][16];
    __shared__ float a_sh[16][129];
    __shared__ float tcs[NBR];

    for (int i = tid; i < NBR*16; i += 256) {
        int m = i >> 4, dg = i & 15;
        V4[m][dg] = *(const float4*)&g_Vh[((size_t)mb*NBR + m)*HD + dg*4];
    }
    if (tid < NBR) tcs[tid] = g_tcb[bb*NBR + tid];
    __syncthreads();

    const int nn = tid >> 4, mg = tid & 15;
    const int n = n0 + nn;
    const float rmv = g_rowmax[mb*NBR + n];
    const float t = g_thresh[mb];
    const float* llr = g_ll + ((size_t)mb*NBR + n)*NBR;
    const float* prr = g_prior + ((size_t)mb*NBR + n)*NBR;
    float psum = 0.f;
    #pragma unroll
    for (int k = 0; k < 8; k++) {
        int m = mg + 16*k;
        float sel = (prr[m] >= t) ? 1e4f : 0.f;
        float a = __expf(llr[m] - rmv - sel) * tcs[m];
        a_sh[nn][m] = a;
        psum += a;
    }
    #pragma unroll
    for (int off = 8; off >= 1; off >>= 1)
        psum += __shfl_xor_sync(0xffffffffu, psum, off, 16);
    if (mg == 0) g_low_norm[mb*NBR + n] = psum;
    __syncthreads();

    {
        const int dg = tid & 15;
        const float* ar = a_sh[tid >> 4];
        float4 acc = make_float4(0.f, 0.f, 0.f, 0.f);
        #pragma unroll 8
        for (int m = 0; m < NBR; m++) {
            float av = ar[m];
            float4 v = V4[m][dg];
            acc.x += av*v.x; acc.y += av*v.y; acc.z += av*v.z; acc.w += av*v.w;
        }
        *(float4*)&g_low_out[((size_t)mb*NBR + n0 + (tid >> 4))*HD + dg*4] = acc;
    }
}

// ---------------- kernel 6: high-res attention (R12 loop body) + fused combine ----------------
#define SKH 0
#define SKL 8192
#define SVH 16384
#define SVL 24576
#define SQH 32768
#define SQL 36864
#define SMK 40960
#define SPH 41216
#define SPL 43776
#define SMAXP 46336
#define SSUMP 46848
#define SRM 47360
#define SSC 47488
#define SNRM 47616
#define SMBR 47744
#define HR_SMEM 47872

__global__ __launch_bounds__(128) void highres_kernel(const float* __restrict__ mask,
                                                      float* __restrict__ gout)
{
    __shared__ __align__(128) char sm[HR_SMEM];
    __shared__ float QM[32];
    __shared__ float LOWR[64];
    __shared__ float s_rmb, s_ln;
    const uint32_t sb = smem_u32(sm);
    const int mbn = blockIdx.x;
    const int mb = mbn >> 7, q = mbn & 127;
    const int bb = mb / Hh, hh = mb % Hh;
    const int tid = threadIdx.x;
    const int lane = tid & 31, w = tid >> 5;

    const int nb = g_cnt[mbn];
    const int* lst = g_list + (size_t)mbn*NBR;

    float* RM  = (float*)(sm + SRM);
    float* SC  = (float*)(sm + SSC);
    float* NRM = (float*)(sm + SNRM);
    float* MAXP = (float*)(sm + SMAXP);
    float* SUMP = (float*)(sm + SSUMP);

    {
        size_t qtb = ((size_t)mb*128 + q)*4096;
        const uint4* qh = (const uint4*)((const char*)g_Qbh + qtb);
        const uint4* ql = (const uint4*)((const char*)g_Qbl + qtb);
        for (int i = tid; i < 256; i += 128) {
            ((uint4*)(sm + SQH))[i] = qh[i];
            ((uint4*)(sm + SQL))[i] = ql[i];
        }
    }
    if (tid == 0) { MB_INIT(sb + SMBR, 1); MB_INIT(sb + SMBR + 8, 1); }
    if (tid < 32) {
        RM[tid] = -1e30f; NRM[tid] = 0.f;
        QM[tid] = mask[(size_t)bb*Ss + q*BLKSZ + tid];
    }
    if (tid >= 64 && tid < 128) LOWR[tid - 64] = g_low_out[((size_t)mb*NBR + q)*HD + tid - 64];
    if (tid == 32) s_rmb = g_rowmax[mb*NBR + q];
    if (tid == 33) s_ln = g_low_norm[mb*NBR + q];
    __syncthreads();

    uint32_t aQh[2][4][4], aQl[2][4][4];
    #pragma unroll
    for (int mt = 0; mt < 2; mt++) {
        int row = mt*16 + (lane & 7) + ((lane >> 3) & 1)*8;
        #pragma unroll
        for (int ks = 0; ks < 4; ks++) {
            int cell = ks*2 + (lane >> 4);
            uint32_t ad = sb + SQH + row*128 + ((cell ^ (row & 7)) << 4);
            ldsm4(aQh[mt][ks][0], aQh[mt][ks][1], aQh[mt][ks][2], aQh[mt][ks][3], ad);
            ldsm4(aQl[mt][ks][0], aQl[mt][ks][1], aQl[mt][ks][2], aQl[mt][ks][3], ad + 4096);
        }
    }
    __syncthreads();

    float o[2][2][4];
    #pragma unroll
    for (int mt = 0; mt < 2; mt++)
        #pragma unroll
        for (int nt = 0; nt < 2; nt++)
            #pragma unroll
            for (int j = 0; j < 4; j++) o[mt][nt][j] = 0.f;

    #define HR_ISSUE(st, kb) do { if (tid == 0) { \
        uint32_t _mb = sb + SMBR + (st)*8; \
        MB_ARRIVE_TX(_mb, 16512); \
        size_t _tb = ((size_t)mb*128 + (kb))*4096; \
        BULK_G2S(sb + SKH + (st)*4096, (const char*)g_Kbh + _tb, 4096, _mb); \
        BULK_G2S(sb + SKL + (st)*4096, (const char*)g_Kbl + _tb, 4096, _mb); \
        BULK_G2S(sb + SVH + (st)*4096, (const char*)g_Vbh + _tb, 4096, _mb); \
        BULK_G2S(sb + SVL + (st)*4096, (const char*)g_Vbl + _tb, 4096, _mb); \
        BULK_G2S(sb + SMK + (st)*128, (const char*)(mask + (size_t)bb*Ss + (size_t)(kb)*BLKSZ), 128, _mb); \
    } } while (0)

    if (nb > 0) HR_ISSUE(0, lst[0]);

    for (int it = 0; it < nb; it++) {
        const int cur = it & 1;
        if (it + 1 < nb) HR_ISSUE((it+1) & 1, lst[it+1]);
        MB_WAIT(sb + SMBR + cur*8, (it >> 1) & 1);
        __syncthreads();

        float sacc[2][4];
        #pragma unroll
        for (int mt = 0; mt < 2; mt++)
            #pragma unroll
            for (int j = 0; j < 4; j++) sacc[mt][j] = 0.f;

        const uint32_t khb = sb + SKH + cur*4096;
        uint32_t kbh[4][2], kbl[4][2];
        #pragma unroll
        for (int ks = 0; ks < 4; ks++) {
            int kr = 8*w + (lane & 7);
            int cell = ks*2 + ((lane >> 3) & 1);
            uint32_t baddr = khb + kr*128 + ((cell ^ (kr & 7)) << 4);
            ldsm2(kbh[ks][0], kbh[ks][1], baddr);
            ldsm2(kbl[ks][0], kbl[ks][1], baddr + 8192);
        }
        #pragma unroll
        for (int ks = 0; ks < 4; ks++) {
            #pragma unroll
            for (int mt = 0; mt < 2; mt++) {
                mma16816(sacc[mt], aQh[mt][ks][0], aQh[mt][ks][1], aQh[mt][ks][2], aQh[mt][ks][3], kbh[ks][0], kbh[ks][1]);
                mma16816(sacc[mt], aQh[mt][ks][0], aQh[mt][ks][1], aQh[mt][ks][2], aQh[mt][ks][3], kbl[ks][0], kbl[ks][1]);
                mma16816(sacc[mt], aQl[mt][ks][0], aQl[mt][ks][1], aQl[mt][ks][2], aQl[mt][ks][3], kbh[ks][0], kbh[ks][1]);
            }
        }
        #pragma unroll
        for (int mt = 0; mt < 2; mt++)
            #pragma unroll
            for (int j = 0; j < 4; j++) sacc[mt][j] *= 0.125f;

        #pragma unroll
        for (int mt = 0; mt < 2; mt++) {
            float m1 = fmaxf(sacc[mt][0], sacc[mt][1]);
            float m2 = fmaxf(sacc[mt][2], sacc[mt][3]);
            m1 = fmaxf(m1, __shfl_xor_sync(0xffffffffu, m1, 1, 4));
            m1 = fmaxf(m1, __shfl_xor_sync(0xffffffffu, m1, 2, 4));
            m2 = fmaxf(m2, __shfl_xor_sync(0xffffffffu, m2, 1, 4));
            m2 = fmaxf(m2, __shfl_xor_sync(0xffffffffu, m2, 2, 4));
            if ((lane & 3) == 0) {
                int r1 = mt*16 + (lane >> 2);
                MAXP[r1*4 + w] = m1;
                MAXP[(r1+8)*4 + w] = m2;
            }
        }
        __syncthreads();
        if (tid < 32) {
            float tm = fmaxf(fmaxf(MAXP[tid*4], MAXP[tid*4+1]), fmaxf(MAXP[tid*4+2], MAXP[tid*4+3]));
            float old = RM[tid];
            float nm = fmaxf(old, tm);
            SC[tid] = __expf(old - nm);
            RM[tid] = nm;
        }
        __syncthreads();

        const float kmv0 = ((const float*)(sm + SMK + cur*128))[8*w + (lane & 3)*2];
        const float kmv1 = ((const float*)(sm + SMK + cur*128))[8*w + (lane & 3)*2 + 1];
        const float pen0 = 1e4f*(1.f - kmv0), pen1 = 1e4f*(1.f - kmv1);
        const int colb = (8*w + (lane & 3)*2)*2;

        #pragma unroll
        for (int mt = 0; mt < 2; mt++) {
            int r1 = mt*16 + (lane >> 2), r2 = r1 + 8;
            float sc1 = SC[r1], sc2 = SC[r2];
            float rm1 = RM[r1], rm2 = RM[r2];
            #pragma unroll
            for (int nt = 0; nt < 2; nt++) {
                o[mt][nt][0] *= sc1; o[mt][nt][1] *= sc1;
                o[mt][nt][2] *= sc2; o[mt][nt][3] *= sc2;
            }
            float p00, p01, p10, p11;
            if (mt == 0) {
                p00 = __expf(sacc[mt][0] - rm1 - pen0);
                p01 = __expf(sacc[mt][1] - rm1 - pen1);
                p10 = __expf(sacc[mt][2] - rm2 - pen0);
                p11 = fexp_poly(sacc[mt][3] - rm2 - pen1);
            } else {
                p00 = __expf(sacc[mt][0] - rm1 - pen0);
                p01 = __expf(sacc[mt][1] - rm1 - pen1);
                p10 = fexp_poly(sacc[mt][2] - rm2 - pen0);
                p11 = fexp_poly(sacc[mt][3] - rm2 - pen1);
            }

            __nv_bfloat162 ph0 = __floats2bfloat162_rn(p00, p01);
            __nv_bfloat162 pl0 = __floats2bfloat162_rn(
                p00 - __bfloat162float(__low2bfloat16(ph0)),
                p01 - __bfloat162float(__high2bfloat16(ph0)));
            __nv_bfloat162 ph1 = __floats2bfloat162_rn(p10, p11);
            __nv_bfloat162 pl1 = __floats2bfloat162_rn(
                p10 - __bfloat162float(__low2bfloat16(ph1)),
                p11 - __bfloat162float(__high2bfloat16(ph1)));
            *(__nv_bfloat162*)(sm + SPH + r1*80 + colb) = ph0;
            *(__nv_bfloat162*)(sm + SPL + r1*80 + colb) = pl0;
            *(__nv_bfloat162*)(sm + SPH + r2*80 + colb) = ph1;
            *(__nv_bfloat162*)(sm + SPL + r2*80 + colb) = pl1;

            float s1 = p00 + p01, s2 = p10 + p11;
            s1 += __shfl_xor_sync(0xffffffffu, s1, 1, 4);
            s1 += __shfl_xor_sync(0xffffffffu, s1, 2, 4);
            s2 += __shfl_xor_sync(0xffffffffu, s2, 1, 4);
            s2 += __shfl_xor_sync(0xffffffffu, s2, 2, 4);
            if ((lane & 3) == 0) {
                SUMP[r1*4 + w] = s1;
                SUMP[r2*4 + w] = s2;
            }
        }
        __syncthreads();
        if (tid < 32) {
            float s = SUMP[tid*4] + SUMP[tid*4+1] + SUMP[tid*4+2] + SUMP[tid*4+3];
            NRM[tid] = NRM[tid]*SC[tid] + s;
        }

        const uint32_t vhb = sb + SVH + cur*4096;
        #pragma unroll
        for (int ks = 0; ks < 2; ks++) {
            uint32_t aPh[2][4], aPl[2][4];
            #pragma unroll
            for (int mt = 0; mt < 2; mt++) {
                int row = mt*16 + (lane & 7) + ((lane >> 3) & 1)*8;
                uint32_t pad = sb + SPH + row*80 + (ks*2 + (lane >> 4))*16;
                ldsm4(aPh[mt][0], aPh[mt][1], aPh[mt][2], aPh[mt][3], pad);
                ldsm4(aPl[mt][0], aPl[mt][1], aPl[mt][2], aPl[mt][3], pad + (SPL - SPH));
            }
            int vrow = ks*16 + (lane & 7) + ((lane >> 3) & 1)*8;
            int vcell = 2*w + (lane >> 4);
            uint32_t vad = vhb + vrow*128 + ((vcell ^ (vrow & 7)) << 4);
            uint32_t bh0, bh1, bh2, bh3, bl0, bl1, bl2, bl3;
            ldsm4t(bh0, bh1, bh2, bh3, vad);
            ldsm4t(bl0, bl1, bl2, bl3, vad + 8192);
            #pragma unroll
            for (int mt = 0; mt < 2; mt++) {
                mma16816(o[mt][0], aPh[mt][0], aPh[mt][1], aPh[mt][2], aPh[mt][3], bh0, bh1);
                mma16816(o[mt][1], aPh[mt][0], aPh[mt][1], aPh[mt][2], aPh[mt][3], bh2, bh3);
                mma16816(o[mt][0], aPh[mt][0], aPh[mt][1], aPh[mt][2], aPh[mt][3], bl0, bl1);
                mma16816(o[mt][1], aPh[mt][0], aPh[mt][1], aPh[mt][2], aPh[mt][3], bl2, bl3);
                mma16816(o[mt][0], aPl[mt][0], aPl[mt][1], aPl[mt][2], aPl[mt][3], bh0, bh1);
                mma16816(o[mt][1], aPl[mt][0], aPl[mt][1], aPl[mt][2], aPl[mt][3], bh2, bh3);
            }
        }
        __syncthreads();
    }

    // ---- fused combine epilogue ----
    const float rmb = s_rmb, lnv = s_ln;
    #pragma unroll
    for (int mt = 0; mt < 2; mt++) {
        int r1 = mt*16 + (lane >> 2), r2 = r1 + 8;
        float mx1 = fmaxf(RM[r1], -1e6f), mx2 = fmaxf(RM[r2], -1e6f);
        float lcl1 = (rmb - mx1)*QM[r1], lcl2 = (rmb - mx2)*QM[r2];
        float lc1 = __expf(fminf(lcl1, 0.f)), hc1 = __expf(-fmaxf(lcl1, 0.f));
        float lc2 = __expf(fminf(lcl2, 0.f)), hc2 = __expf(-fmaxf(lcl2, 0.f));
        float inv1 = 1.f/(NRM[r1]*hc1 + lnv*lc1 + 1e-6f);
        float inv2 = 1.f/(NRM[r2]*hc2 + lnv*lc2 + 1e-6f);
        float* op1 = gout + ((size_t)bb*Ss + q*BLKSZ + r1)*Dm + hh*HD;
        float* op2 = gout + ((size_t)bb*Ss + q*BLKSZ + r2)*Dm + hh*HD;
        #pragma unroll
        for (int nt = 0; nt < 2; nt++) {
            int col = 16*w + nt*8 + (lane & 3)*2;
            float2 w1, w2;
            w1.x = (o[mt][nt][0]*hc1 + LOWR[col]*lc1)*inv1;
            w1.y = (o[mt][nt][1]*hc1 + LOWR[col+1]*lc1)*inv1;
            w2.x = (o[mt][nt][2]*hc2 + LOWR[col]*lc2)*inv2;
            w2.y = (o[mt][nt][3]*hc2 + LOWR[col+1]*lc2)*inv2;
            *(float2*)(op1 + col) = w1;
            *(float2*)(op2 + col) = w2;
        }
    }
}

// ---------------- launch ----------------
extern "C" void kernel_launch(void* const* d_in, const int* in_sizes, int n_in,
                              void* d_out, int out_size)
{
    const float* X    = (const float*)d_in[0];
    const float* mask = (const float*)d_in[1];
    const float* Wq   = (const float*)d_in[2];
    const float* bq   = (const float*)d_in[3];
    const float* Wk   = (const float*)d_in[4];
    const float* bk   = (const float*)d_in[5];
    const float* Wv   = (const float*)d_in[6];
    const float* bv   = (const float*)d_in[7];
    float* out = (float*)d_out;

    cudaFuncSetAttribute(qkv_mma_kernel, cudaFuncAttributeMaxDynamicSharedMemorySize, GEMM_SMEM);
    cudaFuncSetAttribute(threshsel_kernel, cudaFuncAttributeMaxDynamicSharedMemorySize, TS_SMEM);

    convX_kernel<<<MROWS*96/256, 256>>>(X);                        // 1
    convW_kernel<<<dim3(Dm*96/256, 3), 256>>>(Wq, Wk, Wv);         // 2
    xbar_kernel<<<Bb*NBR, Dm>>>(X, mask);                          // 3
    qkv_mma_kernel<<<dim3(MROWS/128, 9), 256, GEMM_SMEM>>>(mask, bq, bk, bv);  // 4
    hmean_gemm_kernel<<<dim3(8, 6, 3), 256>>>(Wq, Wk, Wv, bq, bk, bv);         // 5
    lowlogit_kernel<<<dim3(8, MBT), 256>>>();                      // 6
    threshsel_kernel<<<MBT, 256, TS_SMEM>>>();                     // 7
    lowres_kernel<<<dim3(8, MBT), 256>>>();                        // 8
    highres_kernel<<<MBT*NBR, 128>>>(mask, out);                   // 9 (writes final out)
}

// round 15
// speedup vs baseline: 1.0578x; 1.0162x over previous
#include <cuda_runtime.h>
#include <cuda_bf16.h>
#include <cstdint>

// ---------------- problem constants ----------------
#define Bb 2
#define Ss 4096
#define Dm 768
#define Hh 12
#define HD 64
#define BLKSZ 32
#define NBR 128
#define NUMBLK 1024
#define MBT (Bb*Hh)        // 24
#define MROWS (Bb*Ss)      // 8192

typedef unsigned long long ull;

__device__ __forceinline__ uint32_t smem_u32(const void* p) {
    uint32_t a;
    asm("{ .reg .u64 t; cvta.to.shared.u64 t, %1; cvt.u32.u64 %0, t; }" : "=r"(a) : "l"(p));
    return a;
}

// ---------------- mbarrier + bulk-copy helpers ----------------
#define MB_INIT(mb, c) \
    asm volatile("mbarrier.init.shared.b64 [%0], %1;" :: "r"((uint32_t)(mb)), "r"((uint32_t)(c)) : "memory")
#define MB_ARRIVE_TX(mb, bytes) \
    asm volatile("mbarrier.arrive.expect_tx.shared.b64 _, [%0], %1;" :: "r"((uint32_t)(mb)), "r"((uint32_t)(bytes)) : "memory")
#define BULK_G2S(dst, src, size, mb) \
    asm volatile("cp.async.bulk.shared::cluster.global.mbarrier::complete_tx::bytes [%0], [%1], %2, [%3];" \
        :: "r"((uint32_t)(dst)), "l"(src), "r"((uint32_t)(size)), "r"((uint32_t)(mb)) : "memory")
#define MB_WAIT(mb, ph) do { \
    uint32_t _m = (uint32_t)(mb); uint32_t _p = (uint32_t)(ph); uint32_t _d; \
    asm volatile("{\n\t.reg .pred p;\n\tmbarrier.try_wait.parity.acquire.cta.shared::cta.b64 p, [%1], %2;\n\tselp.b32 %0, 1, 0, p;\n\t}" \
        : "=r"(_d) : "r"(_m), "r"(_p) : "memory"); \
    if (!_d) { \
        asm volatile("{\n\t.reg .pred P1;\n\tWL_%=:\n\tmbarrier.try_wait.parity.acquire.cta.shared::cta.b64 P1, [%0], %1, 0x989680;\n\t@P1 bra.uni WD_%=;\n\tbra.uni WL_%=;\n\tWD_%=:\n\t}" \
            :: "r"(_m), "r"(_p) : "memory"); \
    } } while (0)

// ---------------- mma.sync helpers ----------------
__device__ __forceinline__ void ldsm4(uint32_t &r0, uint32_t &r1, uint32_t &r2, uint32_t &r3, uint32_t addr) {
    asm volatile("ldmatrix.sync.aligned.m8n8.x4.shared.b16 {%0,%1,%2,%3}, [%4];"
        : "=r"(r0), "=r"(r1), "=r"(r2), "=r"(r3) : "r"(addr));
}
__device__ __forceinline__ void ldsm2(uint32_t &r0, uint32_t &r1, uint32_t addr) {
    asm volatile("ldmatrix.sync.aligned.m8n8.x2.shared.b16 {%0,%1}, [%2];"
        : "=r"(r0), "=r"(r1) : "r"(addr));
}
__device__ __forceinline__ void ldsm4t(uint32_t &r0, uint32_t &r1, uint32_t &r2, uint32_t &r3, uint32_t addr) {
    asm volatile("ldmatrix.sync.aligned.m8n8.x4.trans.shared.b16 {%0,%1,%2,%3}, [%4];"
        : "=r"(r0), "=r"(r1), "=r"(r2), "=r"(r3) : "r"(addr));
}
__device__ __forceinline__ void mma16816(float* c,
    uint32_t a0, uint32_t a1, uint32_t a2, uint32_t a3, uint32_t b0, uint32_t b1) {
    asm volatile("mma.sync.aligned.m16n8k16.row.col.f32.bf16.bf16.f32 "
        "{%0,%1,%2,%3}, {%4,%5,%6,%7}, {%8,%9}, {%0,%1,%2,%3};"
        : "+f"(c[0]), "+f"(c[1]), "+f"(c[2]), "+f"(c[3])
        : "r"(a0), "r"(a1), "r"(a2), "r"(a3), "r"(b0), "r"(b1));
}

// ---------------- f32x2 helpers ----------------
__device__ __forceinline__ void ffma2(ull &d, ull a, ull b) {
    asm("fma.rn.f32x2 %0, %1, %2, %0;" : "+l"(d) : "l"(a), "l"(b));
}
__device__ __forceinline__ ull pack2(float x, float y) {
    ull r; asm("mov.b64 %0, {%1, %2};" : "=l"(r) : "f"(x), "f"(y)); return r;
}
__device__ __forceinline__ void unpack2(ull v, float &x, float &y) {
    asm("mov.b64 {%0, %1}, %2;" : "=f"(x), "=f"(y) : "l"(v));
}

// fast exp on the fma/alu pipes
__device__ __forceinline__ float fexp_poly(float x) {
    float z = x * 1.4426950408889634f;
    z = fmaxf(z, -120.f);
    float m = z + 12582912.0f;
    int n = __float_as_int(m) - 0x4B400000;
    float f = z - (m - 12582912.0f);
    float p = 1.3333558e-3f;
    p = fmaf(p, f, 9.6181291e-3f);
    p = fmaf(p, f, 5.5504109e-2f);
    p = fmaf(p, f, 2.4022651e-1f);
    p = fmaf(p, f, 6.9314718e-1f);
    p = fmaf(p, f, 1.0f);
    float r = __int_as_float(__float_as_int(p) + (n << 23));
    return (x < -80.f) ? 0.f : r;
}

// ---------------- device scratch (pre-swizzled blocked layouts) ----------------
__device__ __align__(256) __nv_bfloat16 g_Qbh[MBT*Ss*HD];
__device__ __align__(256) __nv_bfloat16 g_Qbl[MBT*Ss*HD];
__device__ __align__(256) __nv_bfloat16 g_Kbh[MBT*Ss*HD];
__device__ __align__(256) __nv_bfloat16 g_Kbl[MBT*Ss*HD];
__device__ __align__(256) __nv_bfloat16 g_Vbh[MBT*Ss*HD];
__device__ __align__(256) __nv_bfloat16 g_Vbl[MBT*Ss*HD];
__device__ __align__(256) __nv_bfloat16 g_Xh[MROWS*Dm];
__device__ __align__(256) __nv_bfloat16 g_Xl[MROWS*Dm];
__device__ __align__(256) __nv_bfloat16 g_Wh[3*Dm*Dm];
__device__ __align__(256) __nv_bfloat16 g_Wl[3*Dm*Dm];
__device__ float g_Xbar[Bb*NBR*Dm];
__device__ float g_tcb[Bb*NBR];
__device__ float g_tcf[Bb*NBR];
__device__ float g_Qh[MBT*NBR*HD];
__device__ float g_Kh[MBT*NBR*HD];
__device__ float g_Vh[MBT*NBR*HD];
__device__ float g_ll[MBT*NBR*NBR];
__device__ float g_prior[MBT*NBR*NBR];
__device__ float g_rowmax[MBT*NBR];
__device__ float g_thresh[MBT];
__device__ int   g_cnt[MBT*NBR];
__device__ int   g_list[MBT*NBR*NBR];
__device__ float g_low_out[MBT*NBR*HD];
__device__ float g_low_norm[MBT*NBR];

__device__ __forceinline__ unsigned f2ord(float f) {
    unsigned u = __float_as_uint(f);
    return (u & 0x80000000u) ? ~u : (u | 0x80000000u);
}

// ---------------- kernel 0a: split X -> k-chunk-major swizzled bf16 hi/lo ----------------
__global__ void convX_kernel(const float* __restrict__ X)
{
    int idx = blockIdx.x*256 + threadIdx.x;
    int row = idx / 96, cidx = idx % 96;
    int kc = cidx >> 2, c4 = cidx & 3;
    const float* src = X + (size_t)row*Dm + cidx*8;
    float4 v0 = *(const float4*)src;
    float4 v1 = *(const float4*)(src + 4);
    float vf[8] = {v0.x, v0.y, v0.z, v0.w, v1.x, v1.y, v1.z, v1.w};
    __nv_bfloat16 h[8], l[8];
    #pragma unroll
    for (int j = 0; j < 8; j++) {
        h[j] = __float2bfloat16(vf[j]);
        l[j] = __float2bfloat16(vf[j] - __bfloat162float(h[j]));
    }
    size_t dst = ((size_t)kc*MROWS + row)*64 + ((c4 ^ ((row>>1)&3))<<4);
    *(uint4*)((char*)g_Xh + dst) = *(uint4*)h;
    *(uint4*)((char*)g_Xl + dst) = *(uint4*)l;
}

// ---------------- kernel 0b: split W -> k-chunk-major swizzled bf16 hi/lo ----------------
__global__ void convW_kernel(const float* __restrict__ Wq,
                             const float* __restrict__ Wk,
                             const float* __restrict__ Wv)
{
    int mat = blockIdx.y;
    const float* W = (mat == 0) ? Wq : (mat == 1) ? Wk : Wv;
    int idx = blockIdx.x*256 + threadIdx.x;
    int n = idx / 96, cidx = idx % 96;
    int kc = cidx >> 2, c4 = cidx & 3;
    const float* src = W + (size_t)n*Dm + cidx*8;
    float4 v0 = *(const float4*)src;
    float4 v1 = *(const float4*)(src + 4);
    float vf[8] = {v0.x, v0.y, v0.z, v0.w, v1.x, v1.y, v1.z, v1.w};
    __nv_bfloat16 h[8], l[8];
    #pragma unroll
    for (int j = 0; j < 8; j++) {
        h[j] = __float2bfloat16(vf[j]);
        l[j] = __float2bfloat16(vf[j] - __bfloat162float(h[j]));
    }
    size_t dst = (((size_t)mat*24 + kc)*Dm + n)*64 + ((c4 ^ ((n>>1)&3))<<4);
    *(uint4*)((char*)g_Wh + dst) = *(uint4*)h;
    *(uint4*)((char*)g_Wl + dst) = *(uint4*)l;
}

// ---------------- kernel 0c: masked block-mean of X ----------------
__global__ void xbar_kernel(const float* __restrict__ X, const float* __restrict__ mask)
{
    int bn = blockIdx.x;
    int bb = bn >> 7, n = bn & 127;
    int d = threadIdx.x;
    const float* mrow = mask + (size_t)bb*Ss + n*BLKSZ;
    float tc = 0.f;
    #pragma unroll
    for (int t = 0; t < BLKSZ; t++) tc += mrow[t];
    float denom = tc + 1e-6f;
    const float* xp = X + ((size_t)bb*Ss + n*BLKSZ)*Dm + d;
    float s = 0.f;
    #pragma unroll 4
    for (int t = 0; t < BLKSZ; t++) s += mrow[t]*xp[(size_t)t*Dm];
    g_Xbar[(size_t)bn*Dm + d] = s/denom;
    if (d == 0) { g_tcb[bn] = tc; g_tcf[bn] = tc/denom; }
}

// ---------------- kernel 1: QKV projection, bulk pipeline, 64x64 warp tiles ----------------
#define QSTG 49152
#define QMBAR (3*QSTG)
#define GEMM_SMEM (QMBAR + 64)

__global__ __launch_bounds__(256, 1) void qkv_mma_kernel(
    const float* __restrict__ mask,
    const float* __restrict__ bq, const float* __restrict__ bk, const float* __restrict__ bv)
{
    extern __shared__ __align__(128) char smem[];
    const uint32_t sb = smem_u32(smem);
    const int tid = threadIdx.x, lane = tid & 31, wid = tid >> 5;
    const int m0 = blockIdx.x * 128;
    const int tile = blockIdx.y;          // 0..8
    const int mat = tile / 3;
    const int n0 = (tile % 3) * 256;
    const int wm = wid & 1;               // m strip of 64
    const int wn = wid >> 1;              // n strip of 64

    const float* bias = (mat == 0) ? bq : (mat == 1) ? bk : bv;
    __nv_bfloat16* outH = (mat == 0) ? g_Qbh : (mat == 1) ? g_Kbh : g_Vbh;
    __nv_bfloat16* outL = (mat == 0) ? g_Qbl : (mat == 1) ? g_Kbl : g_Vbl;

    if (tid == 0) {
        MB_INIT(sb + QMBAR + 0, 1);
        MB_INIT(sb + QMBAR + 8, 1);
        MB_INIT(sb + QMBAR + 16, 1);
    }
    __syncthreads();

    float acc[4][8][4];
    #pragma unroll
    for (int a = 0; a < 4; a++)
        #pragma unroll
        for (int b = 0; b < 8; b++)
            #pragma unroll
            for (int c = 0; c < 4; c++) acc[a][b][c] = 0.f;

    #define QISSUE(s) do { if (tid == 0) { \
        const int _b = (s) % 3; \
        const uint32_t _bb = sb + _b*QSTG; \
        const uint32_t _mb = sb + QMBAR + _b*8; \
        MB_ARRIVE_TX(_mb, 49152); \
        BULK_G2S(_bb,         (const char*)g_Xh + ((size_t)(s)*MROWS + m0)*64, 8192, _mb); \
        BULK_G2S(_bb + 8192,  (const char*)g_Xl + ((size_t)(s)*MROWS + m0)*64, 8192, _mb); \
        BULK_G2S(_bb + 16384, (const char*)g_Wh + (((size_t)mat*24 + (s))*Dm + n0)*64, 16384, _mb); \
        BULK_G2S(_bb + 32768, (const char*)g_Wl + (((size_t)mat*24 + (s))*Dm + n0)*64, 16384, _mb); \
    } } while (0)

    QISSUE(0);
    QISSUE(1);

    for (int s = 0; s < 24; s++) {
        MB_WAIT(sb + QMBAR + (s % 3)*8, (s / 3) & 1);
        __syncthreads();
        if (s + 2 < 24) QISSUE(s + 2);
        const uint32_t base = sb + (s % 3)*QSTG;

        #pragma unroll
        for (int kk = 0; kk < 2; kk++) {
            uint32_t ah[4][4], al[4][4];
            #pragma unroll
            for (int mt = 0; mt < 4; mt++) {
                int row = wm*64 + mt*16 + (lane & 7) + ((lane >> 3) & 1)*8;
                int cell = kk*2 + (lane >> 4);
                uint32_t ad = base + row*64 + ((cell ^ ((row >> 1) & 3)) << 4);
                ldsm4(ah[mt][0], ah[mt][1], ah[mt][2], ah[mt][3], ad);
                ldsm4(al[mt][0], al[mt][1], al[mt][2], al[mt][3], ad + 8192);
            }
            #pragma unroll
            for (int np = 0; np < 4; np++) {
                int n = wn*64 + np*16 + (lane & 7) + ((lane >> 4) << 3);
                int cellB = kk*2 + ((lane >> 3) & 1);
                uint32_t bd = base + 16384 + n*64 + ((cellB ^ ((n >> 1) & 3)) << 4);
                uint32_t b0, b1, b2, b3, c0, c1, c2, c3;
                ldsm4(b0, b1, b2, b3, bd);
                ldsm4(c0, c1, c2, c3, bd + 16384);
                #pragma unroll
                for (int mt = 0; mt < 4; mt++) {
                    mma16816(acc[mt][np*2],   ah[mt][0], ah[mt][1], ah[mt][2], ah[mt][3], b0, b1);
                    mma16816(acc[mt][np*2+1], ah[mt][0], ah[mt][1], ah[mt][2], ah[mt][3], b2, b3);
                    mma16816(acc[mt][np*2],   al[mt][0], al[mt][1], al[mt][2], al[mt][3], b0, b1);
                    mma16816(acc[mt][np*2+1], al[mt][0], al[mt][1], al[mt][2], al[mt][3], b2, b3);
                    mma16816(acc[mt][np*2],   ah[mt][0], ah[mt][1], ah[mt][2], ah[mt][3], c0, c1);
                    mma16816(acc[mt][np*2+1], ah[mt][0], ah[mt][1], ah[mt][2], ah[mt][3], c2, c3);
                }
            }
        }
    }

    const int h = (n0 + wn*64) >> 6;
    const float* bp = bias + n0 + wn*64;
    float2 bias2[8];
    #pragma unroll
    for (int nt = 0; nt < 8; nt++) bias2[nt] = *(const float2*)(bp + nt*8 + (lane & 3)*2);

    #pragma unroll
    for (int mt = 0; mt < 4; mt++) {
        #pragma unroll
        for (int half = 0; half < 2; half++) {
            int m = m0 + wm*64 + mt*16 + (lane >> 2) + half*8;
            int bbm = m >> 12, sx = m & 4095;
            float mv = mask[(size_t)bbm*Ss + sx];
            int mb_ = bbm*Hh + h, kb = sx >> 5, r = sx & 31;
            size_t tb = ((size_t)(mb_*128 + kb)*32 + r)*64;
            #pragma unroll
            for (int nt = 0; nt < 8; nt++) {
                size_t off = tb + ((nt ^ (r & 7)) << 3) + (lane & 3)*2;
                float wx = (acc[mt][nt][half*2+0] + bias2[nt].x)*mv;
                float wy = (acc[mt][nt][half*2+1] + bias2[nt].y)*mv;
                __nv_bfloat162 hv = __floats2bfloat162_rn(wx, wy);
                float hx = __bfloat162float(__low2bfloat16(hv));
                float hy = __bfloat162float(__high2bfloat16(hv));
                __nv_bfloat162 lv = __floats2bfloat162_rn(wx - hx, wy - hy);
                *(__nv_bfloat162*)(outH + off) = hv;
                *(__nv_bfloat162*)(outL + off) = lv;
            }
        }
    }
}

// ---------------- kernel 1b: exact fp32 block-mean projection (f32x2) ----------------
__global__ __launch_bounds__(256) void hmean_gemm_kernel(
    const float* __restrict__ Wq, const float* __restrict__ Wk, const float* __restrict__ Wv,
    const float* __restrict__ bq, const float* __restrict__ bk, const float* __restrict__ bv)
{
    __shared__ float As[32][33];
    __shared__ float Bs[128][33];

    const int mat = blockIdx.z;
    const float* W = (mat == 0) ? Wq : (mat == 1) ? Wk : Wv;
    const float* bias = (mat == 0) ? bq : (mat == 1) ? bk : bv;
    float* out = (mat == 0) ? g_Qh : (mat == 1) ? g_Kh : g_Vh;

    const int tid = threadIdx.x;
    const int r0 = blockIdx.x * 32;
    const int e0 = blockIdx.y * 128;
    const int tn = tid >> 4;
    const int tm2 = tid & 15;

    ull acc2[8];
    #pragma unroll
    for (int j = 0; j < 8; j++) acc2[j] = 0ull;

    for (int k0 = 0; k0 < Dm; k0 += 32) {
        {
            int r = tid >> 3, kq = tid & 7;
            float4 v = *(const float4*)&g_Xbar[(size_t)(r0 + r)*Dm + k0 + kq*4];
            As[r][kq*4+0] = v.x; As[r][kq*4+1] = v.y; As[r][kq*4+2] = v.z; As[r][kq*4+3] = v.w;
        }
        #pragma unroll
        for (int t = 0; t < 4; t++) {
            int idx = tid + t*256;
            int r = idx >> 3, kq = idx & 7;
            float4 v = *(const float4*)&W[(size_t)(e0 + r)*Dm + k0 + kq*4];
            Bs[r][kq*4+0] = v.x; Bs[r][kq*4+1] = v.y; Bs[r][kq*4+2] = v.z; Bs[r][kq*4+3] = v.w;
        }
        __syncthreads();
        #pragma unroll 8
        for (int k = 0; k < 32; k++) {
            ull a2 = pack2(As[tm2*2][k], As[tm2*2+1][k]);
            #pragma unroll
            for (int j = 0; j < 8; j++) {
                float b = Bs[tn*8+j][k];
                ffma2(acc2[j], a2, pack2(b, b));
            }
        }
        __syncthreads();
    }

    #pragma unroll
    for (int j = 0; j < 8; j++) {
        float v0, v1;
        unpack2(acc2[j], v0, v1);
        int e = e0 + tn*8 + j;
        int hh = e >> 6, hd = e & 63;
        #pragma unroll
        for (int i = 0; i < 2; i++) {
            const int r = r0 + tm2*2 + i;
            const int bb2 = r >> 7, n = r & 127;
            const float tcf = g_tcf[r];
            out[(((size_t)(bb2*Hh + hh))*NBR + n)*HD + hd] = (i ? v1 : v0) + bias[e]*tcf;
        }
    }
}

// ---------------- kernel 3: low-res logits (16 q-rows per CTA) ----------------
__global__ __launch_bounds__(256) void lowlogit_kernel()
{
    const int mb = blockIdx.y, q0 = blockIdx.x*16;
    const int bb = mb / Hh;
    const int tid = threadIdx.x;
    __shared__ float Kt[64][129];
    __shared__ float Qhs[16][65];
    __shared__ float tcs[NBR];

    for (int i = tid; i < NBR*HD; i += 256) {
        int m = i >> 6, d = i & 63;
        Kt[d][m] = g_Kh[((size_t)mb*NBR + m)*HD + d];
    }
    for (int i = tid; i < 16*HD; i += 256) {
        int qq = i >> 6, d = i & 63;
        Qhs[qq][d] = g_Qh[((size_t)mb*NBR + q0 + qq)*HD + d];
    }
    if (tid < NBR) tcs[tid] = g_tcb[bb*NBR + tid];
    __syncthreads();

    const int q = tid >> 4, mg = tid & 15;
    float s[8];
    #pragma unroll
    for (int k = 0; k < 8; k++) s[k] = 0.f;
    for (int d = 0; d < HD; d++) {
        float qv = Qhs[q][d];
        const float* kr = &Kt[d][mg];
        #pragma unroll
        for (int k = 0; k < 8; k++) s[k] += qv*kr[16*k];
    }
    #pragma unroll
    for (int k = 0; k < 8; k++) s[k] *= 0.125f;

    float mx = s[0];
    #pragma unroll
    for (int k = 1; k < 8; k++) mx = fmaxf(mx, s[k]);
    #pragma unroll
    for (int off = 8; off >= 1; off >>= 1)
        mx = fmaxf(mx, __shfl_xor_sync(0xffffffffu, mx, off, 16));
    const int n = q0 + q;
    if (mg == 0) g_rowmax[mb*NBR + n] = mx;

    const float tcn = tcs[n];
    float* llr = g_ll + ((size_t)mb*NBR + n)*NBR;
    float* prr = g_prior + ((size_t)mb*NBR + n)*NBR;
    #pragma unroll
    for (int k = 0; k < 8; k++) {
        int m = mg + 16*k;
        float pe = (tcn*tcs[m] < 0.5f) ? 1.0f : 0.0f;
        float ll = s[k] - 1e4f*pe;
        float prior = ll - mx;
        int dif = n - m; if (dif < 0) dif = -dif;
        if (dif <= 1) prior += 5e3f;
        llr[m] = ll;
        prr[m] = prior;
    }
}

// ---------------- kernel 4+5 merged: radix threshold + select (1024 threads) ----------------
#define TS_SMEM (NBR*NBR*4 + 256*4 + 16)
__global__ __launch_bounds__(1024) void threshsel_kernel()
{
    extern __shared__ __align__(16) float ts_sm[];
    float* prs = ts_sm;
    unsigned* hist = (unsigned*)(ts_sm + NBR*NBR);
    unsigned* ctrl = hist + 256;

    const int mb = blockIdx.x;
    const int tid = threadIdx.x;
    const int lane = tid & 31;
    const float* pr = g_prior + (size_t)mb*NBR*NBR;
    for (int i = tid; i < NBR*NBR; i += 1024) prs[i] = pr[i];
    if (tid == 0) { ctrl[0] = 0u; ctrl[1] = NUMBLK; }
    __syncthreads();

    for (int pass = 0; pass < 4; pass++) {
        int shift = 24 - pass*8;
        if (tid < 256) hist[tid] = 0u;
        __syncthreads();
        unsigned pref = ctrl[0];
        for (int i = tid; i < NBR*NBR; i += 1024) {
            unsigned u = f2ord(prs[i]);
            bool ok = (pass == 0) ? true : (((u ^ pref) >> (shift + 8)) == 0u);
            unsigned bin = ok ? ((u >> shift) & 255u) : 0xFFFFFFFFu;
            unsigned mm = __match_any_sync(0xffffffffu, bin);
            if (bin != 0xFFFFFFFFu && (__ffs(mm) - 1) == lane)
                atomicAdd(&hist[bin], __popc(mm));
        }
        __syncthreads();
        if (tid == 0) {
            int k = (int)ctrl[1]; unsigned cum = 0u; int sel = 0;
            for (int bbin = 255; bbin >= 0; bbin--) {
                unsigned h = hist[bbin];
                if (cum + h >= (unsigned)k) { sel = bbin; break; }
                cum += h;
            }
            ctrl[1] = (unsigned)(k - (int)cum);
            ctrl[0] = pref | ((unsigned)sel << shift);
        }
        __syncthreads();
    }
    float t;
    {
        unsigned u = ctrl[0];
        unsigned raw = (u & 0x80000000u) ? (u & 0x7FFFFFFFu) : ~u;
        t = __uint_as_float(raw);
    }
    if (tid == 0) g_thresh[mb] = t;

    if (tid < 128) {
        const int n = tid;
        const float* prow = prs + n*NBR;
        int* lst = g_list + ((size_t)mb*NBR + n)*NBR;
        int c = 0;
        for (int m = 0; m < NBR; m++)
            if (prow[m] >= t) lst[c++] = m;
        g_cnt[mb*NBR + n] = c;
    }
}

// ---------------- kernel 7: low-res attention (16 n-rows per CTA) ----------------
__global__ __launch_bounds__(256) void lowres_kernel()
{
    const int mb = blockIdx.y, n0 = blockIdx.x*16;
    const int bb = mb / Hh;
    const int tid = threadIdx.x;
    __shared__ float4 V4[NBR][16];
    __shared__ float a_sh[16][129];
    __shared__ float tcs[NBR];

    for (int i = tid; i < NBR*16; i += 256) {
        int m = i >> 4, dg = i & 15;
        V4[m][dg] = *(const float4*)&g_Vh[((size_t)mb*NBR + m)*HD + dg*4];
    }
    if (tid < NBR) tcs[tid] = g_tcb[bb*NBR + tid];
    __syncthreads();

    const int nn = tid >> 4, mg = tid & 15;
    const int n = n0 + nn;
    const float rmv = g_rowmax[mb*NBR + n];
    const float t = g_thresh[mb];
    const float* llr = g_ll + ((size_t)mb*NBR + n)*NBR;
    const float* prr = g_prior + ((size_t)mb*NBR + n)*NBR;
    float psum = 0.f;
    #pragma unroll
    for (int k = 0; k < 8; k++) {
        int m = mg + 16*k;
        float sel = (prr[m] >= t) ? 1e4f : 0.f;
        float a = __expf(llr[m] - rmv - sel) * tcs[m];
        a_sh[nn][m] = a;
        psum += a;
    }
    #pragma unroll
    for (int off = 8; off >= 1; off >>= 1)
        psum += __shfl_xor_sync(0xffffffffu, psum, off, 16);
    if (mg == 0) g_low_norm[mb*NBR + n] = psum;
    __syncthreads();

    {
        const int dg = tid & 15;
        const float* ar = a_sh[tid >> 4];
        float4 acc = make_float4(0.f, 0.f, 0.f, 0.f);
        #pragma unroll 8
        for (int m = 0; m < NBR; m++) {
            float av = ar[m];
            float4 v = V4[m][dg];
            acc.x += av*v.x; acc.y += av*v.y; acc.z += av*v.z; acc.w += av*v.w;
        }
        *(float4*)&g_low_out[((size_t)mb*NBR + n0 + (tid >> 4))*HD + dg*4] = acc;
    }
}

// ---------------- kernel 6: high-res attention + fused combine (lean softmax) ----------------
#define SKH 0
#define SKL 8192
#define SVH 16384
#define SVL 24576
#define SQH 32768
#define SQL 36864
#define SMK 40960
#define SPH 41216
#define SPL 43776
#define SMAXP 46336
#define SRM 46848
#define SSC 46976
#define SMBR 47104
#define HR_SMEM 47232

__global__ __launch_bounds__(128) void highres_kernel(const float* __restrict__ mask,
                                                      float* __restrict__ gout)
{
    __shared__ __align__(128) char sm[HR_SMEM];
    __shared__ float QM[32];
    __shared__ float LOWR[64];
    __shared__ float s_rmb, s_ln;
    const uint32_t sb = smem_u32(sm);
    const int mbn = blockIdx.x;
    const int mb = mbn >> 7, q = mbn & 127;
    const int bb = mb / Hh, hh = mb % Hh;
    const int tid = threadIdx.x;
    const int lane = tid & 31, w = tid >> 5;
    const uint32_t ONES2 = 0x3F803F80u;   // {1.0bf16, 1.0bf16}

    const int nb = g_cnt[mbn];
    const int* lst = g_list + (size_t)mbn*NBR;

    float* RM  = (float*)(sm + SRM);
    float* SC  = (float*)(sm + SSC);
    float* MAXP = (float*)(sm + SMAXP);

    {
        size_t qtb = ((size_t)mb*128 + q)*4096;
        const uint4* qh = (const uint4*)((const char*)g_Qbh + qtb);
        const uint4* ql = (const uint4*)((const char*)g_Qbl + qtb);
        for (int i = tid; i < 256; i += 128) {
            ((uint4*)(sm + SQH))[i] = qh[i];
            ((uint4*)(sm + SQL))[i] = ql[i];
        }
    }
    if (tid == 0) { MB_INIT(sb + SMBR, 1); MB_INIT(sb + SMBR + 8, 1); }
    if (tid < 32) {
        RM[tid] = -1e30f;
        QM[tid] = mask[(size_t)bb*Ss + q*BLKSZ + tid];
    }
    if (tid >= 64 && tid < 128) LOWR[tid - 64] = g_low_out[((size_t)mb*NBR + q)*HD + tid - 64];
    if (tid == 32) s_rmb = g_rowmax[mb*NBR + q];
    if (tid == 33) s_ln = g_low_norm[mb*NBR + q];
    __syncthreads();

    uint32_t aQh[2][4][4], aQl[2][4][4];
    #pragma unroll
    for (int mt = 0; mt < 2; mt++) {
        int row = mt*16 + (lane & 7) + ((lane >> 3) & 1)*8;
        #pragma unroll
        for (int ks = 0; ks < 4; ks++) {
            int cell = ks*2 + (lane >> 4);
            uint32_t ad = sb + SQH + row*128 + ((cell ^ (row & 7)) << 4);
            ldsm4(aQh[mt][ks][0], aQh[mt][ks][1], aQh[mt][ks][2], aQh[mt][ks][3], ad);
            ldsm4(aQl[mt][ks][0], aQl[mt][ks][1], aQl[mt][ks][2], aQl[mt][ks][3], ad + 4096);
        }
    }
    __syncthreads();

    float o[2][2][4];
    float nracc[2][4];
    #pragma unroll
    for (int mt = 0; mt < 2; mt++) {
        #pragma unroll
        for (int nt = 0; nt < 2; nt++)
            #pragma unroll
            for (int j = 0; j < 4; j++) o[mt][nt][j] = 0.f;
        #pragma unroll
        for (int j = 0; j < 4; j++) nracc[mt][j] = 0.f;
    }

    #define HR_ISSUE(st, kb) do { if (tid == 0) { \
        uint32_t _mb = sb + SMBR + (st)*8; \
        MB_ARRIVE_TX(_mb, 16512); \
        size_t _tb = ((size_t)mb*128 + (kb))*4096; \
        BULK_G2S(sb + SKH + (st)*4096, (const char*)g_Kbh + _tb, 4096, _mb); \
        BULK_G2S(sb + SKL + (st)*4096, (const char*)g_Kbl + _tb, 4096, _mb); \
        BULK_G2S(sb + SVH + (st)*4096, (const char*)g_Vbh + _tb, 4096, _mb); \
        BULK_G2S(sb + SVL + (st)*4096, (const char*)g_Vbl + _tb, 4096, _mb); \
        BULK_G2S(sb + SMK + (st)*128, (const char*)(mask + (size_t)bb*Ss + (size_t)(kb)*BLKSZ), 128, _mb); \
    } } while (0)

    if (nb > 0) HR_ISSUE(0, lst[0]);

    for (int it = 0; it < nb; it++) {
        const int cur = it & 1;
        if (it + 1 < nb) HR_ISSUE((it+1) & 1, lst[it+1]);
        MB_WAIT(sb + SMBR + cur*8, (it >> 1) & 1);
        __syncthreads();

        // ---- S = Qh*Kh + Qh*Kl + Ql*Kh (raw, unscaled) ----
        float sacc[2][4];
        #pragma unroll
        for (int mt = 0; mt < 2; mt++)
            #pragma unroll
            for (int j = 0; j < 4; j++) sacc[mt][j] = 0.f;

        const uint32_t khb = sb + SKH + cur*4096;
        uint32_t kbh[4][2], kbl[4][2];
        #pragma unroll
        for (int ks = 0; ks < 4; ks++) {
            int kr = 8*w + (lane & 7);
            int cell = ks*2 + ((lane >> 3) & 1);
            uint32_t baddr = khb + kr*128 + ((cell ^ (kr & 7)) << 4);
            ldsm2(kbh[ks][0], kbh[ks][1], baddr);
            ldsm2(kbl[ks][0], kbl[ks][1], baddr + 8192);
        }
        #pragma unroll
        for (int ks = 0; ks < 4; ks++) {
            #pragma unroll
            for (int mt = 0; mt < 2; mt++) {
                mma16816(sacc[mt], aQh[mt][ks][0], aQh[mt][ks][1], aQh[mt][ks][2], aQh[mt][ks][3], kbh[ks][0], kbh[ks][1]);
                mma16816(sacc[mt], aQh[mt][ks][0], aQh[mt][ks][1], aQh[mt][ks][2], aQh[mt][ks][3], kbl[ks][0], kbl[ks][1]);
                mma16816(sacc[mt], aQl[mt][ks][0], aQl[mt][ks][1], aQl[mt][ks][2], aQl[mt][ks][3], kbh[ks][0], kbh[ks][1]);
            }
        }

        // per-warp partial row max (scaled once after reduce)
        #pragma unroll
        for (int mt = 0; mt < 2; mt++) {
            float m1 = fmaxf(sacc[mt][0], sacc[mt][1]);
            float m2 = fmaxf(sacc[mt][2], sacc[mt][3]);
            m1 = fmaxf(m1, __shfl_xor_sync(0xffffffffu, m1, 1, 4));
            m1 = fmaxf(m1, __shfl_xor_sync(0xffffffffu, m1, 2, 4));
            m2 = fmaxf(m2, __shfl_xor_sync(0xffffffffu, m2, 1, 4));
            m2 = fmaxf(m2, __shfl_xor_sync(0xffffffffu, m2, 2, 4));
            if ((lane & 3) == 0) {
                int r1 = mt*16 + (lane >> 2);
                MAXP[r1*4 + w] = m1*0.125f;
                MAXP[(r1+8)*4 + w] = m2*0.125f;
            }
        }
        __syncthreads();
        if (tid < 32) {
            float tm = fmaxf(fmaxf(MAXP[tid*4], MAXP[tid*4+1]), fmaxf(MAXP[tid*4+2], MAXP[tid*4+3]));
            float old = RM[tid];
            float nm = fmaxf(old, tm);
            SC[tid] = __expf(old - nm);
            RM[tid] = nm;
        }
        __syncthreads();

        const float kmv0 = ((const float*)(sm + SMK + cur*128))[8*w + (lane & 3)*2];
        const float kmv1 = ((const float*)(sm + SMK + cur*128))[8*w + (lane & 3)*2 + 1];
        const bool allone = __ballot_sync(0xffffffffu, kmv0 == 1.f && kmv1 == 1.f) == 0xffffffffu;
        const int colb = (8*w + (lane & 3)*2)*2;

        #pragma unroll
        for (int mt = 0; mt < 2; mt++) {
            int r1 = mt*16 + (lane >> 2), r2 = r1 + 8;
            float sc1 = SC[r1], sc2 = SC[r2];
            float rm1 = RM[r1], rm2 = RM[r2];
            #pragma unroll
            for (int nt = 0; nt < 2; nt++) {
                o[mt][nt][0] *= sc1; o[mt][nt][1] *= sc1;
                o[mt][nt][2] *= sc2; o[mt][nt][3] *= sc2;
            }
            nracc[mt][0] *= sc1;
            nracc[mt][2] *= sc2;

            float b10, b11, b20, b21;
            if (allone) { b10 = b11 = -rm1; b20 = b21 = -rm2; }
            else {
                float pen0 = 1e4f*(1.f - kmv0), pen1 = 1e4f*(1.f - kmv1);
                b10 = -(rm1 + pen0); b11 = -(rm1 + pen1);
                b20 = -(rm2 + pen0); b21 = -(rm2 + pen1);
            }
            float p00, p01, p10, p11;
            if (mt == 0) {
                p00 = __expf(fmaf(sacc[mt][0], 0.125f, b10));
                p01 = __expf(fmaf(sacc[mt][1], 0.125f, b11));
                p10 = __expf(fmaf(sacc[mt][2], 0.125f, b20));
                p11 = fexp_poly(fmaf(sacc[mt][3], 0.125f, b21));
            } else {
                p00 = __expf(fmaf(sacc[mt][0], 0.125f, b10));
                p01 = __expf(fmaf(sacc[mt][1], 0.125f, b11));
                p10 = fexp_poly(fmaf(sacc[mt][2], 0.125f, b20));
                p11 = fexp_poly(fmaf(sacc[mt][3], 0.125f, b21));
            }

            __nv_bfloat162 ph0 = __floats2bfloat162_rn(p00, p01);
            __nv_bfloat162 pl0 = __floats2bfloat162_rn(
                p00 - __bfloat162float(__low2bfloat16(ph0)),
                p01 - __bfloat162float(__high2bfloat16(ph0)));
            __nv_bfloat162 ph1 = __floats2bfloat162_rn(p10, p11);
            __nv_bfloat162 pl1 = __floats2bfloat162_rn(
                p10 - __bfloat162float(__low2bfloat16(ph1)),
                p11 - __bfloat162float(__high2bfloat16(ph1)));
            *(__nv_bfloat162*)(sm + SPH + r1*80 + colb) = ph0;
            *(__nv_bfloat162*)(sm + SPL + r1*80 + colb) = pl0;
            *(__nv_bfloat162*)(sm + SPH + r2*80 + colb) = ph1;
            *(__nv_bfloat162*)(sm + SPL + r2*80 + colb) = pl1;
        }
        __syncthreads();   // P ready

        const uint32_t vhb = sb + SVH + cur*4096;
        #pragma unroll
        for (int ks = 0; ks < 2; ks++) {
            uint32_t aPh[2][4], aPl[2][4];
            #pragma unroll
            for (int mt = 0; mt < 2; mt++) {
                int row = mt*16 + (lane & 7) + ((lane >> 3) & 1)*8;
                uint32_t pad = sb + SPH + row*80 + (ks*2 + (lane >> 4))*16;
                ldsm4(aPh[mt][0], aPh[mt][1], aPh[mt][2], aPh[mt][3], pad);
                ldsm4(aPl[mt][0], aPl[mt][1], aPl[mt][2], aPl[mt][3], pad + (SPL - SPH));
            }
            int vrow = ks*16 + (lane & 7) + ((lane >> 3) & 1)*8;
            int vcell = 2*w + (lane >> 4);
            uint32_t vad = vhb + vrow*128 + ((vcell ^ (vrow & 7)) << 4);
            uint32_t bh0, bh1, bh2, bh3, bl0, bl1, bl2, bl3;
            ldsm4t(bh0, bh1, bh2, bh3, vad);
            ldsm4t(bl0, bl1, bl2, bl3, vad + 8192);
            #pragma unroll
            for (int mt = 0; mt < 2; mt++) {
                mma16816(o[mt][0], aPh[mt][0], aPh[mt][1], aPh[mt][2], aPh[mt][3], bh0, bh1);
                mma16816(o[mt][1], aPh[mt][0], aPh[mt][1], aPh[mt][2], aPh[mt][3], bh2, bh3);
                mma16816(o[mt][0], aPh[mt][0], aPh[mt][1], aPh[mt][2], aPh[mt][3], bl0, bl1);
                mma16816(o[mt][1], aPh[mt][0], aPh[mt][1], aPh[mt][2], aPh[mt][3], bl2, bl3);
                mma16816(o[mt][0], aPl[mt][0], aPl[mt][1], aPl[mt][2], aPl[mt][3], bh0, bh1);
                mma16816(o[mt][1], aPl[mt][0], aPl[mt][1], aPl[mt][2], aPl[mt][3], bh2, bh3);
                // nrm row-sums on the tensor pipe: P · ones
                mma16816(nracc[mt], aPh[mt][0], aPh[mt][1], aPh[mt][2], aPh[mt][3], ONES2, ONES2);
                mma16816(nracc[mt], aPl[mt][0], aPl[mt][1], aPl[mt][2], aPl[mt][3], ONES2, ONES2);
            }
        }
        __syncthreads();
    }

    // ---- fused combine epilogue ----
    const float rmb = s_rmb, lnv = s_ln;
    #pragma unroll
    for (int mt = 0; mt < 2; mt++) {
        int r1 = mt*16 + (lane >> 2), r2 = r1 + 8;
        float mx1 = fmaxf(RM[r1], -1e6f), mx2 = fmaxf(RM[r2], -1e6f);
        float lcl1 = (rmb - mx1)*QM[r1], lcl2 = (rmb - mx2)*QM[r2];
        float lc1 = __expf(fminf(lcl1, 0.f)), hc1 = __expf(-fmaxf(lcl1, 0.f));
        float lc2 = __expf(fminf(lcl2, 0.f)), hc2 = __expf(-fmaxf(lcl2, 0.f));
        float inv1 = 1.f/(nracc[mt][0]*hc1 + lnv*lc1 + 1e-6f);
        float inv2 = 1.f/(nracc[mt][2]*hc2 + lnv*lc2 + 1e-6f);
        float* op1 = gout + ((size_t)bb*Ss + q*BLKSZ + r1)*Dm + hh*HD;
        float* op2 = gout + ((size_t)bb*Ss + q*BLKSZ + r2)*Dm + hh*HD;
        #pragma unroll
        for (int nt = 0; nt < 2; nt++) {
            int col = 16*w + nt*8 + (lane & 3)*2;
            float2 w1, w2;
            w1.x = (o[mt][nt][0]*hc1 + LOWR[col]*lc1)*inv1;
            w1.y = (o[mt][nt][1]*hc1 + LOWR[col+1]*lc1)*inv1;
            w2.x = (o[mt][nt][2]*hc2 + LOWR[col]*lc2)*inv2;
            w2.y = (o[mt][nt][3]*hc2 + LOWR[col+1]*lc2)*inv2;
            *(float2*)(op1 + col) = w1;
            *(float2*)(op2 + col) = w2;
        }
    }
}

// ---------------- launch ----------------
extern "C" void kernel_launch(void* const* d_in, const int* in_sizes, int n_in,
                              void* d_out, int out_size)
{
    const float* X    = (const float*)d_in[0];
    const float* mask = (const float*)d_in[1];
    const float* Wq   = (const float*)d_in[2];
    const float* bq   = (const float*)d_in[3];
    const float* Wk   = (const float*)d_in[4];
    const float* bk   = (const float*)d_in[5];
    const float* Wv   = (const float*)d_in[6];
    const float* bv   = (const float*)d_in[7];
    float* out = (float*)d_out;

    cudaFuncSetAttribute(qkv_mma_kernel, cudaFuncAttributeMaxDynamicSharedMemorySize, GEMM_SMEM);
    cudaFuncSetAttribute(threshsel_kernel, cudaFuncAttributeMaxDynamicSharedMemorySize, TS_SMEM);

    convX_kernel<<<MROWS*96/256, 256>>>(X);                        // 1
    convW_kernel<<<dim3(Dm*96/256, 3), 256>>>(Wq, Wk, Wv);         // 2
    xbar_kernel<<<Bb*NBR, Dm>>>(X, mask);                          // 3
    qkv_mma_kernel<<<dim3(MROWS/128, 9), 256, GEMM_SMEM>>>(mask, bq, bk, bv);  // 4
    hmean_gemm_kernel<<<dim3(8, 6, 3), 256>>>(Wq, Wk, Wv, bq, bk, bv);         // 5
    lowlogit_kernel<<<dim3(8, MBT), 256>>>();                      // 6
    threshsel_kernel<<<MBT, 1024, TS_SMEM>>>();                    // 7
    lowres_kernel<<<dim3(8, MBT), 256>>>();                        // 8
    highres_kernel<<<MBT*NBR, 128>>>(mask, out);                   // 9 (writes final out)
}